// round 1
// baseline (speedup 1.0000x reference)
#include <cuda_runtime.h>
#include <cuda_bf16.h>
#include <math.h>

// ---------------- problem constants ----------------
#define E_   2
#define HQ_  16
#define HK_  8
#define HD_  128
#define DIM_ 2048
#define BS_  2
#define SEQ_ 2048
#define NTOK (BS_*SEQ_)          // 4096
#define EPS_ 1e-6f
#define SCALE_ 0.08838834764831845f   // 1/sqrt(128)

// ---------------- scratch (device globals; no cudaMalloc allowed) ----------------
__device__ float g_q [NTOK * (HQ_*HD_)];   // 4096 x 2048
__device__ float g_k [NTOK * (HK_*HD_)];   // 4096 x 1024
__device__ float g_v [NTOK * (HK_*HD_)];   // 4096 x 1024
__device__ float g_ao[NTOK * (HQ_*HD_)];   // attention out, token-major
__device__ float g_o [NTOK * DIM_];        // WO output before final rmsnorm

// ============================================================================
// GEMM with per-row (per-token) expert selection.
// C[n][c] = sum_k A[n][k] * W[mod[n]][k][c]
// A: [NTOK][K] row-major; W: [2][K][NC] row-major; C: [NTOK][NC]
// Tile: 128x128, K-chunk 16, 256 threads, 8x8 microtile.
// Both experts' B tiles live in smem; selection is an FSEL per (i,j).
// ============================================================================
__global__ __launch_bounds__(256) void gemm_select(
    const float* __restrict__ A, const float* __restrict__ W,
    const int* __restrict__ mod, float* __restrict__ C,
    int K, int NC)
{
    __shared__ float sA[16][128];
    __shared__ float sB[2][16][128];
    const int tid = threadIdx.x;
    const int tx = tid & 15, ty = tid >> 4;
    const int bm = blockIdx.y * 128, bn = blockIdx.x * 128;

    float acc[8][8];
#pragma unroll
    for (int i = 0; i < 8; i++)
#pragma unroll
        for (int j = 0; j < 8; j++) acc[i][j] = 0.f;

    unsigned em = 0;
#pragma unroll
    for (int i = 0; i < 8; i++)
        em |= ((unsigned)mod[bm + ty*8 + i] & 1u) << i;

    for (int k0 = 0; k0 < K; k0 += 16) {
        // A tile -> smem transposed: sA[k][m]
#pragma unroll
        for (int u = 0; u < 2; u++) {
            int idx = tid*2 + u;          // 0..511
            int row = idx >> 2;           // 0..127
            int kq  = idx & 3;            // 0..3 (float4 within 16 k's)
            float4 v = *(const float4*)(A + (size_t)(bm+row)*K + k0 + kq*4);
            sA[kq*4+0][row] = v.x; sA[kq*4+1][row] = v.y;
            sA[kq*4+2][row] = v.z; sA[kq*4+3][row] = v.w;
        }
        // B tiles, both experts
#pragma unroll
        for (int e = 0; e < 2; e++) {
            const float* We = W + (size_t)e*K*NC + (size_t)k0*NC + bn;
#pragma unroll
            for (int u = 0; u < 2; u++) {
                int idx = tid*2 + u;      // 0..511
                int kk = idx >> 5;        // 0..15
                int n4 = idx & 31;        // 0..31
                *(float4*)&sB[e][kk][n4*4] = *(const float4*)(We + (size_t)kk*NC + n4*4);
            }
        }
        __syncthreads();
#pragma unroll
        for (int k = 0; k < 16; k++) {
            float a[8], b0[8], b1[8];
#pragma unroll
            for (int i = 0; i < 8; i += 4) {
                float4 t = *(float4*)&sA[k][ty*8 + i];
                a[i]=t.x; a[i+1]=t.y; a[i+2]=t.z; a[i+3]=t.w;
            }
#pragma unroll
            for (int j = 0; j < 8; j += 4) {
                float4 t0 = *(float4*)&sB[0][k][tx*8 + j];
                b0[j]=t0.x; b0[j+1]=t0.y; b0[j+2]=t0.z; b0[j+3]=t0.w;
                float4 t1 = *(float4*)&sB[1][k][tx*8 + j];
                b1[j]=t1.x; b1[j+1]=t1.y; b1[j+2]=t1.z; b1[j+3]=t1.w;
            }
#pragma unroll
            for (int i = 0; i < 8; i++) {
                bool hi = (em >> i) & 1;
#pragma unroll
                for (int j = 0; j < 8; j++) {
                    float bb = hi ? b1[j] : b0[j];
                    acc[i][j] = fmaf(a[i], bb, acc[i][j]);
                }
            }
        }
        __syncthreads();
    }
#pragma unroll
    for (int i = 0; i < 8; i++)
#pragma unroll
        for (int j = 0; j < 8; j += 4) {
            float4 v = make_float4(acc[i][j], acc[i][j+1], acc[i][j+2], acc[i][j+3]);
            *(float4*)(C + (size_t)(bm+ty*8+i)*NC + bn + tx*8 + j) = v;
        }
}

// ============================================================================
// Per-head RMSNorm (with weight) followed by RoPE, in place.
// buf: [NTOK][nheads*128]. grid=(NTOK, nheads), block=128.
// Interleaved-pair RoPE: (t0,t1) = (buf[2j], buf[2j+1]).
// ============================================================================
__global__ __launch_bounds__(128) void rmsnorm_rope(
    float* __restrict__ buf, const float* __restrict__ normw,
    const float* __restrict__ fcos, const float* __restrict__ fsin,
    const int* __restrict__ mod, int nheads)
{
    const int n = blockIdx.x;
    const int h = blockIdx.y;
    const int d = threadIdx.x;          // 0..127
    const int s = n & (SEQ_-1);         // position within sequence
    const int e = mod[n];
    float* p = buf + (size_t)n*nheads*HD_ + h*HD_;

    float v = p[d];
    float ss = v * v;
#pragma unroll
    for (int o = 16; o > 0; o >>= 1) ss += __shfl_xor_sync(0xffffffffu, ss, o);
    __shared__ float wsum[4];
    if ((d & 31) == 0) wsum[d >> 5] = ss;
    __syncthreads();
    float tot = wsum[0] + wsum[1] + wsum[2] + wsum[3];
    float r = rsqrtf(tot * (1.0f/HD_) + EPS_);
    v = v * r * normw[e*HD_ + d];

    float partner = __shfl_xor_sync(0xffffffffu, v, 1);
    float c  = fcos[s*(HD_/2) + (d >> 1)];
    float sn = fsin[s*(HD_/2) + (d >> 1)];
    float outv = (d & 1) ? fmaf(partner, sn, v * c)    // odd: t0*s + t1*c
                         : (v * c - partner * sn);     // even: t0*c - t1*s
    p[d] = outv;
}

// ============================================================================
// Causal flash attention, fp32, GQA (kv head = h>>1).
// Block: one (b, h, 64-row q tile). 256 threads = 64 rows x 4 (quad).
// Each thread: 16 interleaved score cols (qd+4i), owns 32 interleaved out cols.
// Padded smem strides (132 / 65) kill the 128-float-row bank conflicts.
// ============================================================================
#define FA_QS   (64*132)
#define FA_FLTS (3*FA_QS + 64*65)
#define FA_BYTES (FA_FLTS*4)

__global__ __launch_bounds__(256) void flash_attn(
    const float* __restrict__ Q, const float* __restrict__ Kb,
    const float* __restrict__ Vb, float* __restrict__ O)
{
    extern __shared__ float sm[];
    float* Qs = sm;
    float* Ks = Qs + FA_QS;
    float* Vs = Ks + FA_QS;
    float* Ps = Vs + FA_QS;     // 64 x 65

    const int tid = threadIdx.x;
    const int r  = tid >> 2;    // q row 0..63
    const int qd = tid & 3;     // quad lane
    int bx = blockIdx.x;
    const int qt = bx & 31; bx >>= 5;
    const int h  = bx & 15; const int b = bx >> 4;
    const int kvh = h >> 1;
    const int qglob = qt*64 + r;

    // Q tile
    for (int i = tid; i < 64*32; i += 256) {
        int row = i >> 5, c4 = i & 31;
        *(float4*)&Qs[row*132 + c4*4] =
            *(const float4*)&Q[((size_t)(b*SEQ_ + qt*64 + row))*(HQ_*HD_) + h*HD_ + c4*4];
    }

    float m = -1e30f, l = 0.f;
    float o[32];
#pragma unroll
    for (int j = 0; j < 32; j++) o[j] = 0.f;

    for (int kt = 0; kt <= qt; kt++) {
        __syncthreads();   // prior iteration's Vs/Ps reads done (also covers Qs fill)
        for (int i = tid; i < 64*32; i += 256) {
            int row = i >> 5, c4 = i & 31;
            size_t src = ((size_t)(b*SEQ_ + kt*64 + row))*(HK_*HD_) + kvh*HD_ + c4*4;
            *(float4*)&Ks[row*132 + c4*4] = *(const float4*)&Kb[src];
            *(float4*)&Vs[row*132 + c4*4] = *(const float4*)&Vb[src];
        }
        __syncthreads();

        // S = Q K^T for this thread's 16 interleaved cols
        float s[16];
#pragma unroll
        for (int i = 0; i < 16; i++) s[i] = 0.f;
        for (int d4 = 0; d4 < 32; d4++) {
            float4 q4 = *(float4*)&Qs[r*132 + d4*4];
#pragma unroll
            for (int i = 0; i < 16; i++) {
                int kc = qd + 4*i;
                float4 k4 = *(float4*)&Ks[kc*132 + d4*4];
                s[i] += q4.x*k4.x + q4.y*k4.y + q4.z*k4.z + q4.w*k4.w;
            }
        }
        float mt = -1e30f;
#pragma unroll
        for (int i = 0; i < 16; i++) {
            int kg = kt*64 + qd + 4*i;
            s[i] = (kg <= qglob) ? s[i]*SCALE_ : -1e30f;
            mt = fmaxf(mt, s[i]);
        }
        mt = fmaxf(mt, __shfl_xor_sync(0xffffffffu, mt, 1));
        mt = fmaxf(mt, __shfl_xor_sync(0xffffffffu, mt, 2));
        float mnew = fmaxf(m, mt);
        float corr = __expf(m - mnew);
        float psum = 0.f;
#pragma unroll
        for (int i = 0; i < 16; i++) {
            float pv = __expf(s[i] - mnew);
            Ps[r*65 + qd + 4*i] = pv;
            psum += pv;
        }
        psum += __shfl_xor_sync(0xffffffffu, psum, 1);
        psum += __shfl_xor_sync(0xffffffffu, psum, 2);
        l = l*corr + psum;
        m = mnew;
#pragma unroll
        for (int j = 0; j < 32; j++) o[j] *= corr;
        __syncwarp();      // quad-mates' Ps visible

        // O += P V, thread owns 8 interleaved float4 column chunks
        for (int kc = 0; kc < 64; kc++) {
            float pv = Ps[r*65 + kc];
#pragma unroll
            for (int j4 = 0; j4 < 8; j4++) {
                float4 v = *(float4*)&Vs[kc*132 + (qd + 4*j4)*4];
                o[j4*4+0] = fmaf(pv, v.x, o[j4*4+0]);
                o[j4*4+1] = fmaf(pv, v.y, o[j4*4+1]);
                o[j4*4+2] = fmaf(pv, v.z, o[j4*4+2]);
                o[j4*4+3] = fmaf(pv, v.w, o[j4*4+3]);
            }
        }
    }
    float inv = 1.f / l;
#pragma unroll
    for (int j4 = 0; j4 < 8; j4++) {
        float4 v = make_float4(o[j4*4]*inv, o[j4*4+1]*inv, o[j4*4+2]*inv, o[j4*4+3]*inv);
        *(float4*)&O[((size_t)(b*SEQ_ + qglob))*(HQ_*HD_) + h*HD_ + (qd + 4*j4)*4] = v;
    }
}

// ============================================================================
// Final per-token RMSNorm over DIM with attn_norm_w[expert]
// ============================================================================
__global__ __launch_bounds__(256) void final_rms(
    const float* __restrict__ in, const float* __restrict__ w,
    const int* __restrict__ mod, float* __restrict__ out)
{
    const int n = blockIdx.x;
    const int tid = threadIdx.x;
    const int e = mod[n];
    const float* row = in + (size_t)n*DIM_;
    float vals[8];
    float ss = 0.f;
#pragma unroll
    for (int u = 0; u < 8; u++) {
        float v = row[tid + u*256];
        vals[u] = v;
        ss += v*v;
    }
#pragma unroll
    for (int o = 16; o > 0; o >>= 1) ss += __shfl_xor_sync(0xffffffffu, ss, o);
    __shared__ float wsum[8];
    if ((tid & 31) == 0) wsum[tid >> 5] = ss;
    __syncthreads();
    float tot = 0.f;
#pragma unroll
    for (int i = 0; i < 8; i++) tot += wsum[i];
    float r = rsqrtf(tot * (1.0f/DIM_) + EPS_);
#pragma unroll
    for (int u = 0; u < 8; u++)
        out[(size_t)n*DIM_ + tid + u*256] = vals[u] * r * w[e*DIM_ + tid + u*256];
}

// ============================================================================
// launch
// ============================================================================
extern "C" void kernel_launch(void* const* d_in, const int* in_sizes, int n_in,
                              void* d_out, int out_size)
{
    const float* x    = (const float*)d_in[0];
    const float* fcos = (const float*)d_in[1];
    const float* fsin = (const float*)d_in[2];
    const float* wq   = (const float*)d_in[3];
    const float* wk   = (const float*)d_in[4];
    const float* wv   = (const float*)d_in[5];
    const float* wo   = (const float*)d_in[6];
    const float* qnw  = (const float*)d_in[7];
    const float* knw  = (const float*)d_in[8];
    const float* anw  = (const float*)d_in[9];
    const int*   mod  = (const int*)d_in[10];
    float* out = (float*)d_out;

    float *pq, *pk, *pv, *pao, *po;
    cudaGetSymbolAddress((void**)&pq,  g_q);
    cudaGetSymbolAddress((void**)&pk,  g_k);
    cudaGetSymbolAddress((void**)&pv,  g_v);
    cudaGetSymbolAddress((void**)&pao, g_ao);
    cudaGetSymbolAddress((void**)&po,  g_o);

    cudaFuncSetAttribute(flash_attn, cudaFuncAttributeMaxDynamicSharedMemorySize, FA_BYTES);

    // QKV projections (expert-gathered)
    gemm_select<<<dim3(16, 32), 256>>>(x, wq, mod, pq, DIM_, HQ_*HD_);
    gemm_select<<<dim3( 8, 32), 256>>>(x, wk, mod, pk, DIM_, HK_*HD_);
    gemm_select<<<dim3( 8, 32), 256>>>(x, wv, mod, pv, DIM_, HK_*HD_);

    // per-head rmsnorm + rope (norm BEFORE rope)
    rmsnorm_rope<<<dim3(NTOK, HQ_), 128>>>(pq, qnw, fcos, fsin, mod, HQ_);
    rmsnorm_rope<<<dim3(NTOK, HK_), 128>>>(pk, knw, fcos, fsin, mod, HK_);

    // causal flash attention
    flash_attn<<<BS_*HQ_*(SEQ_/64), 256, FA_BYTES>>>(pq, pk, pv, pao);

    // output projection (expert-gathered) + final rmsnorm
    gemm_select<<<dim3(16, 32), 256>>>(pao, wo, mod, po, HQ_*HD_, DIM_);
    final_rms<<<NTOK, 256>>>(po, anw, mod, out);
}

// round 3
// speedup vs baseline: 2.1689x; 2.1689x over previous
#include <cuda_runtime.h>
#include <cuda_bf16.h>
#include <math.h>
#include <cstdint>

// ---------------- problem constants ----------------
#define E_   2
#define HQ_  16
#define HK_  8
#define HD_  128
#define DIM_ 2048
#define BS_  2
#define SEQ_ 2048
#define NTOK (BS_*SEQ_)          // 4096
#define EPS_ 1e-6f
#define SCALE_ 0.08838834764831845f   // 1/sqrt(128)

// ---------------- scratch (device globals; no cudaMalloc allowed) ----------------
__device__ float g_q [NTOK * (HQ_*HD_)];
__device__ float g_k [NTOK * (HK_*HD_)];
__device__ float g_v [NTOK * (HK_*HD_)];
__device__ float g_ao[NTOK * (HQ_*HD_)];
__device__ float g_o [NTOK * DIM_];
__device__ int   g_perm[NTOK];
__device__ int   g_c0;

// =============================== helpers ===============================
__device__ __forceinline__ uint32_t smem_u32(const void* p) {
    uint32_t a;
    asm("{ .reg .u64 t; cvta.to.shared.u64 t, %1; cvt.u32.u64 %0, t; }" : "=r"(a) : "l"(p));
    return a;
}
#define CP_ASYNC16(dst, src) \
    asm volatile("cp.async.cg.shared.global [%0], [%1], 16;" :: "r"(dst), "l"(src) : "memory")
#define CP_COMMIT() asm volatile("cp.async.commit_group;" ::: "memory")
#define CP_WAIT1()  asm volatile("cp.async.wait_group 1;" ::: "memory")

__device__ __forceinline__ void split_tf32(float x, uint32_t& hi, uint32_t& lo) {
    uint32_t h;
    asm("cvt.rna.tf32.f32 %0, %1;" : "=r"(h) : "f"(x));
    hi = h;
    lo = __float_as_uint(x - __uint_as_float(h));
}
__device__ __forceinline__ void mma1688(float* c, const uint32_t* a, const uint32_t* b) {
    asm volatile("mma.sync.aligned.m16n8k8.row.col.f32.tf32.tf32.f32 "
        "{%0,%1,%2,%3}, {%4,%5,%6,%7}, {%8,%9}, {%0,%1,%2,%3};"
        : "+f"(c[0]), "+f"(c[1]), "+f"(c[2]), "+f"(c[3])
        : "r"(a[0]), "r"(a[1]), "r"(a[2]), "r"(a[3]), "r"(b[0]), "r"(b[1]));
}

// ============================================================================
// Deterministic counting sort of tokens by modality (stable).
// One block, 1024 threads x 4 items. perm: expert0 tokens first, then expert1.
// ============================================================================
__global__ __launch_bounds__(1024) void sort_tokens(const int* __restrict__ mod)
{
    __shared__ int s[1024];
    const int tid = threadIdx.x;
    int m[4]; int cnt = 0;
#pragma unroll
    for (int u = 0; u < 4; u++) { m[u] = mod[tid*4 + u]; cnt += (m[u] == 0); }
    s[tid] = cnt;
    __syncthreads();
    for (int off = 1; off < 1024; off <<= 1) {
        int v = (tid >= off) ? s[tid - off] : 0;
        __syncthreads();
        s[tid] += v;
        __syncthreads();
    }
    const int c0 = s[1023];
    if (tid == 0) g_c0 = c0;
    int r0 = s[tid] - cnt;          // exclusive rank of expert-0 before my items
#pragma unroll
    for (int u = 0; u < 4; u++) {
        int g = tid*4 + u;
        if (m[u] == 0) { g_perm[r0] = g; r0++; }
        else           { g_perm[c0 + g - r0] = g; }
    }
}

// ============================================================================
// 3xTF32 mma.sync GEMM over expert-sorted rows.
// C[perm[p]][c] = sum_k A[perm[p]][k] * W[e(p)][k][c]
// Tile 128x128, BK=32, 128 threads (4 warps, warp tile 64x64), cp.async 2-stage.
// A smem: [m][k] rows of 128B, chunk swizzle (c+m)&7  -> conflict-free frags.
// B smem: [k][n] rows of 512B, chunk swizzle (c+2k)&31 -> conflict-free frags.
// ============================================================================
#define MMK_STAGE 32768      // 16KB A + 16KB B
#define MM_DSMEM  (2*MMK_STAGE)

__device__ __forceinline__ float ld_a(const char* ap, int m, int k) {
    return *(const float*)(ap + m*128 + ((((k>>2) + m) & 7) << 4) + ((k&3)<<2));
}
__device__ __forceinline__ float ld_b(const char* bp, int k, int n) {
    return *(const float*)(bp + k*512 + ((((n>>2) + 2*k) & 31) << 4) + ((n&3)<<2));
}

__global__ __launch_bounds__(128) void mm_tf32(
    const float* __restrict__ A, const float* __restrict__ W,
    float* __restrict__ C, int K, int NC)
{
    extern __shared__ char sm[];
    __shared__ int sPerm[128];
    const int tid  = threadIdx.x;
    const int lane = tid & 31;
    const int w    = tid >> 5;
    const int wm64 = (w & 1) * 64;
    const int wn64 = (w >> 1) * 64;
    const int bn   = blockIdx.x * 128;
    const int by   = blockIdx.y;

    const int c0 = g_c0;
    const int T0 = (c0 + 127) >> 7;
    const int T1 = (NTOK - c0 + 127) >> 7;
    if (by >= T0 + T1) return;
    const int e       = (by < T0) ? 0 : 1;
    const int rowbase = e ? (c0 + (by - T0) * 128) : (by * 128);
    const int limit   = e ? NTOK : c0;
    const float* Wp   = W + (size_t)e * K * NC;

    if (tid < 128) {
        int gs = rowbase + tid;
        sPerm[tid] = g_perm[gs < NTOK ? gs : (NTOK - 1)];
    }
    __syncthreads();

    const uint32_t sb = smem_u32(sm);

    auto load_chunk = [&](int cc, int p) {
        const uint32_t abase = sb + p * MMK_STAGE;
        const uint32_t bbase = abase + 16384;
        const int k0 = cc * 32;
#pragma unroll
        for (int i = 0; i < 8; i++) {             // A: 1024 x 16B
            int idx = tid + (i << 7);
            int row = idx >> 3, cch = idx & 7;
            const float* src = A + (size_t)sPerm[row] * K + k0 + (cch << 2);
            uint32_t dst = abase + (uint32_t)(row * 128) + ((uint32_t)((cch + row) & 7) << 4);
            CP_ASYNC16(dst, src);
        }
#pragma unroll
        for (int i = 0; i < 8; i++) {             // B: 1024 x 16B
            int idx = tid + (i << 7);
            int row = idx >> 5, cch = idx & 31;
            const float* src = Wp + (size_t)(k0 + row) * NC + bn + (cch << 2);
            uint32_t dst = bbase + (uint32_t)(row * 512) + ((uint32_t)((cch + 2 * row) & 31) << 4);
            CP_ASYNC16(dst, src);
        }
    };

    float acc[4][8][4];
#pragma unroll
    for (int i = 0; i < 4; i++)
#pragma unroll
        for (int j = 0; j < 8; j++)
#pragma unroll
            for (int q = 0; q < 4; q++) acc[i][j][q] = 0.f;

    const int NCH = K / 32;
    load_chunk(0, 0); CP_COMMIT();
    load_chunk(1, 1); CP_COMMIT();

    const int lr = lane >> 2;      // 0..7
    const int lc = lane & 3;       // 0..3

    for (int c = 0; c < NCH; c++) {
        CP_WAIT1();
        __syncthreads();
        const char* ap = sm + (c & 1) * MMK_STAGE;
        const char* bp = ap + 16384;
#pragma unroll
        for (int s = 0; s < 4; s++) {
            uint32_t ah[4][4], al[4][4];
#pragma unroll
            for (int i = 0; i < 4; i++) {
                int m0 = wm64 + i * 16 + lr;
                int kk = s * 8 + lc;
                split_tf32(ld_a(ap, m0,     kk    ), ah[i][0], al[i][0]);
                split_tf32(ld_a(ap, m0 + 8, kk    ), ah[i][1], al[i][1]);
                split_tf32(ld_a(ap, m0,     kk + 4), ah[i][2], al[i][2]);
                split_tf32(ld_a(ap, m0 + 8, kk + 4), ah[i][3], al[i][3]);
            }
            uint32_t bh[8][2], bl[8][2];
#pragma unroll
            for (int j = 0; j < 8; j++) {
                int n  = wn64 + j * 8 + lr;
                int kk = s * 8 + lc;
                split_tf32(ld_b(bp, kk,     n), bh[j][0], bl[j][0]);
                split_tf32(ld_b(bp, kk + 4, n), bh[j][1], bl[j][1]);
            }
#pragma unroll
            for (int i = 0; i < 4; i++)
#pragma unroll
                for (int j = 0; j < 8; j++) {
                    mma1688(acc[i][j], ah[i], bh[j]);
                    mma1688(acc[i][j], al[i], bh[j]);
                    mma1688(acc[i][j], ah[i], bl[j]);
                }
        }
        __syncthreads();
        if (c + 2 < NCH) load_chunk(c + 2, c & 1);
        CP_COMMIT();
    }

    // epilogue: scatter rows back to token order
#pragma unroll
    for (int i = 0; i < 4; i++) {
        int lr0 = wm64 + i * 16 + lr;
        bool v0 = (rowbase + lr0)     < limit;
        bool v1 = (rowbase + lr0 + 8) < limit;
        int t0 = v0 ? sPerm[lr0]     : 0;
        int t1 = v1 ? sPerm[lr0 + 8] : 0;
#pragma unroll
        for (int j = 0; j < 8; j++) {
            int cb = bn + wn64 + j * 8 + (lc << 1);
            if (v0) *(float2*)&C[(size_t)t0 * NC + cb] = make_float2(acc[i][j][0], acc[i][j][1]);
            if (v1) *(float2*)&C[(size_t)t1 * NC + cb] = make_float2(acc[i][j][2], acc[i][j][3]);
        }
    }
}

// ============================================================================
// Per-head RMSNorm (with weight) followed by RoPE, in place.
// ============================================================================
__global__ __launch_bounds__(128) void rmsnorm_rope(
    float* __restrict__ buf, const float* __restrict__ normw,
    const float* __restrict__ fcos, const float* __restrict__ fsin,
    const int* __restrict__ mod, int nheads)
{
    const int n = blockIdx.x;
    const int h = blockIdx.y;
    const int d = threadIdx.x;
    const int s = n & (SEQ_-1);
    const int e = mod[n];
    float* p = buf + (size_t)n*nheads*HD_ + h*HD_;

    float v = p[d];
    float ss = v * v;
#pragma unroll
    for (int o = 16; o > 0; o >>= 1) ss += __shfl_xor_sync(0xffffffffu, ss, o);
    __shared__ float wsum[4];
    if ((d & 31) == 0) wsum[d >> 5] = ss;
    __syncthreads();
    float tot = wsum[0] + wsum[1] + wsum[2] + wsum[3];
    float r = rsqrtf(tot * (1.0f/HD_) + EPS_);
    v = v * r * normw[e*HD_ + d];

    float partner = __shfl_xor_sync(0xffffffffu, v, 1);
    float c  = fcos[s*(HD_/2) + (d >> 1)];
    float sn = fsin[s*(HD_/2) + (d >> 1)];
    float outv = (d & 1) ? fmaf(partner, sn, v * c)
                         : (v * c - partner * sn);
    p[d] = outv;
}

// ============================================================================
// Causal flash attention, fp32, GQA (kv head = h>>1).
// ============================================================================
#define FA_QS   (64*132)
#define FA_FLTS (3*FA_QS + 64*65)
#define FA_BYTES (FA_FLTS*4)

__global__ __launch_bounds__(256) void flash_attn(
    const float* __restrict__ Q, const float* __restrict__ Kb,
    const float* __restrict__ Vb, float* __restrict__ O)
{
    extern __shared__ float smf[];
    float* Qs = smf;
    float* Ks = Qs + FA_QS;
    float* Vs = Ks + FA_QS;
    float* Ps = Vs + FA_QS;

    const int tid = threadIdx.x;
    const int r  = tid >> 2;
    const int qd = tid & 3;
    int bx = blockIdx.x;
    const int qt = bx & 31; bx >>= 5;
    const int h  = bx & 15; const int b = bx >> 4;
    const int kvh = h >> 1;
    const int qglob = qt*64 + r;

    for (int i = tid; i < 64*32; i += 256) {
        int row = i >> 5, c4 = i & 31;
        *(float4*)&Qs[row*132 + c4*4] =
            *(const float4*)&Q[((size_t)(b*SEQ_ + qt*64 + row))*(HQ_*HD_) + h*HD_ + c4*4];
    }

    float m = -1e30f, l = 0.f;
    float o[32];
#pragma unroll
    for (int j = 0; j < 32; j++) o[j] = 0.f;

    for (int kt = 0; kt <= qt; kt++) {
        __syncthreads();
        for (int i = tid; i < 64*32; i += 256) {
            int row = i >> 5, c4 = i & 31;
            size_t src = ((size_t)(b*SEQ_ + kt*64 + row))*(HK_*HD_) + kvh*HD_ + c4*4;
            *(float4*)&Ks[row*132 + c4*4] = *(const float4*)&Kb[src];
            *(float4*)&Vs[row*132 + c4*4] = *(const float4*)&Vb[src];
        }
        __syncthreads();

        float s[16];
#pragma unroll
        for (int i = 0; i < 16; i++) s[i] = 0.f;
        for (int d4 = 0; d4 < 32; d4++) {
            float4 q4 = *(float4*)&Qs[r*132 + d4*4];
#pragma unroll
            for (int i = 0; i < 16; i++) {
                int kc = qd + 4*i;
                float4 k4 = *(float4*)&Ks[kc*132 + d4*4];
                s[i] += q4.x*k4.x + q4.y*k4.y + q4.z*k4.z + q4.w*k4.w;
            }
        }
        float mt = -1e30f;
#pragma unroll
        for (int i = 0; i < 16; i++) {
            int kg = kt*64 + qd + 4*i;
            s[i] = (kg <= qglob) ? s[i]*SCALE_ : -1e30f;
            mt = fmaxf(mt, s[i]);
        }
        mt = fmaxf(mt, __shfl_xor_sync(0xffffffffu, mt, 1));
        mt = fmaxf(mt, __shfl_xor_sync(0xffffffffu, mt, 2));
        float mnew = fmaxf(m, mt);
        float corr = __expf(m - mnew);
        float psum = 0.f;
#pragma unroll
        for (int i = 0; i < 16; i++) {
            float pv = __expf(s[i] - mnew);
            Ps[r*65 + qd + 4*i] = pv;
            psum += pv;
        }
        psum += __shfl_xor_sync(0xffffffffu, psum, 1);
        psum += __shfl_xor_sync(0xffffffffu, psum, 2);
        l = l*corr + psum;
        m = mnew;
#pragma unroll
        for (int j = 0; j < 32; j++) o[j] *= corr;
        __syncwarp();

        for (int kc = 0; kc < 64; kc++) {
            float pv = Ps[r*65 + kc];
#pragma unroll
            for (int j4 = 0; j4 < 8; j4++) {
                float4 v = *(float4*)&Vs[kc*132 + (qd + 4*j4)*4];
                o[j4*4+0] = fmaf(pv, v.x, o[j4*4+0]);
                o[j4*4+1] = fmaf(pv, v.y, o[j4*4+1]);
                o[j4*4+2] = fmaf(pv, v.z, o[j4*4+2]);
                o[j4*4+3] = fmaf(pv, v.w, o[j4*4+3]);
            }
        }
    }
    float inv = 1.f / l;
#pragma unroll
    for (int j4 = 0; j4 < 8; j4++) {
        float4 v = make_float4(o[j4*4]*inv, o[j4*4+1]*inv, o[j4*4+2]*inv, o[j4*4+3]*inv);
        *(float4*)&O[((size_t)(b*SEQ_ + qglob))*(HQ_*HD_) + h*HD_ + (qd + 4*j4)*4] = v;
    }
}

// ============================================================================
// Final per-token RMSNorm over DIM with attn_norm_w[expert]
// ============================================================================
__global__ __launch_bounds__(256) void final_rms(
    const float* __restrict__ in, const float* __restrict__ w,
    const int* __restrict__ mod, float* __restrict__ out)
{
    const int n = blockIdx.x;
    const int tid = threadIdx.x;
    const int e = mod[n];
    const float* row = in + (size_t)n*DIM_;
    float vals[8];
    float ss = 0.f;
#pragma unroll
    for (int u = 0; u < 8; u++) {
        float v = row[tid + u*256];
        vals[u] = v;
        ss += v*v;
    }
#pragma unroll
    for (int o = 16; o > 0; o >>= 1) ss += __shfl_xor_sync(0xffffffffu, ss, o);
    __shared__ float wsum[8];
    if ((tid & 31) == 0) wsum[tid >> 5] = ss;
    __syncthreads();
    float tot = 0.f;
#pragma unroll
    for (int i = 0; i < 8; i++) tot += wsum[i];
    float r = rsqrtf(tot * (1.0f/DIM_) + EPS_);
#pragma unroll
    for (int u = 0; u < 8; u++)
        out[(size_t)n*DIM_ + tid + u*256] = vals[u] * r * w[e*DIM_ + tid + u*256];
}

// ============================================================================
// launch
// ============================================================================
extern "C" void kernel_launch(void* const* d_in, const int* in_sizes, int n_in,
                              void* d_out, int out_size)
{
    const float* x    = (const float*)d_in[0];
    const float* fcos = (const float*)d_in[1];
    const float* fsin = (const float*)d_in[2];
    const float* wq   = (const float*)d_in[3];
    const float* wk   = (const float*)d_in[4];
    const float* wv   = (const float*)d_in[5];
    const float* wo   = (const float*)d_in[6];
    const float* qnw  = (const float*)d_in[7];
    const float* knw  = (const float*)d_in[8];
    const float* anw  = (const float*)d_in[9];
    const int*   mod  = (const int*)d_in[10];
    float* out = (float*)d_out;

    float *pq, *pk, *pv, *pao, *po;
    cudaGetSymbolAddress((void**)&pq,  g_q);
    cudaGetSymbolAddress((void**)&pk,  g_k);
    cudaGetSymbolAddress((void**)&pv,  g_v);
    cudaGetSymbolAddress((void**)&pao, g_ao);
    cudaGetSymbolAddress((void**)&po,  g_o);

    cudaFuncSetAttribute(flash_attn, cudaFuncAttributeMaxDynamicSharedMemorySize, FA_BYTES);
    cudaFuncSetAttribute(mm_tf32,    cudaFuncAttributeMaxDynamicSharedMemorySize, MM_DSMEM);

    // sort tokens by expert (deterministic)
    sort_tokens<<<1, 1024>>>(mod);

    // QKV projections (expert-sorted, mma.sync 3xTF32)
    mm_tf32<<<dim3(16, 33), 128, MM_DSMEM>>>(x, wq, pq, DIM_, HQ_*HD_);
    mm_tf32<<<dim3( 8, 33), 128, MM_DSMEM>>>(x, wk, pk, DIM_, HK_*HD_);
    mm_tf32<<<dim3( 8, 33), 128, MM_DSMEM>>>(x, wv, pv, DIM_, HK_*HD_);

    // per-head rmsnorm + rope (norm BEFORE rope)
    rmsnorm_rope<<<dim3(NTOK, HQ_), 128>>>(pq, qnw, fcos, fsin, mod, HQ_);
    rmsnorm_rope<<<dim3(NTOK, HK_), 128>>>(pk, knw, fcos, fsin, mod, HK_);

    // causal flash attention
    flash_attn<<<BS_*HQ_*(SEQ_/64), 256, FA_BYTES>>>(pq, pk, pv, pao);

    // output projection + final rmsnorm
    mm_tf32<<<dim3(16, 33), 128, MM_DSMEM>>>(pao, wo, po, HQ_*HD_, DIM_);
    final_rms<<<NTOK, 256>>>(po, anw, mod, out);
}

// round 4
// speedup vs baseline: 3.4025x; 1.5688x over previous
#include <cuda_runtime.h>
#include <cuda_bf16.h>
#include <math.h>
#include <cstdint>

// ---------------- problem constants ----------------
#define E_   2
#define HQ_  16
#define HK_  8
#define HD_  128
#define DIM_ 2048
#define BS_  2
#define SEQ_ 2048
#define NTOK (BS_*SEQ_)          // 4096
#define EPS_ 1e-6f
#define SCALE_ 0.08838834764831845f   // 1/sqrt(128)

// ---------------- scratch (device globals; no cudaMalloc allowed) ----------------
__device__ float g_q [NTOK * (HQ_*HD_)];
__device__ float g_k [NTOK * (HK_*HD_)];
__device__ float g_v [NTOK * (HK_*HD_)];
__device__ float g_ao[NTOK * (HQ_*HD_)];
__device__ float g_o [NTOK * DIM_];
__device__ int   g_perm[NTOK];
__device__ int   g_c0;

// =============================== helpers ===============================
__device__ __forceinline__ uint32_t smem_u32(const void* p) {
    uint32_t a;
    asm("{ .reg .u64 t; cvta.to.shared.u64 t, %1; cvt.u32.u64 %0, t; }" : "=r"(a) : "l"(p));
    return a;
}
#define CP_ASYNC16(dst, src) \
    asm volatile("cp.async.cg.shared.global [%0], [%1], 16;" :: "r"(dst), "l"(src) : "memory")
#define CP_COMMIT() asm volatile("cp.async.commit_group;" ::: "memory")
#define CP_WAIT1()  asm volatile("cp.async.wait_group 1;" ::: "memory")
template<int N> __device__ __forceinline__ void cp_wait() {
    asm volatile("cp.async.wait_group %0;" :: "n"(N) : "memory");
}

__device__ __forceinline__ void split_tf32(float x, uint32_t& hi, uint32_t& lo) {
    uint32_t h;
    asm("cvt.rna.tf32.f32 %0, %1;" : "=r"(h) : "f"(x));
    hi = h;
    lo = __float_as_uint(x - __uint_as_float(h));
}
__device__ __forceinline__ void mma1688(float* c, const uint32_t* a, const uint32_t* b) {
    asm volatile("mma.sync.aligned.m16n8k8.row.col.f32.tf32.tf32.f32 "
        "{%0,%1,%2,%3}, {%4,%5,%6,%7}, {%8,%9}, {%0,%1,%2,%3};"
        : "+f"(c[0]), "+f"(c[1]), "+f"(c[2]), "+f"(c[3])
        : "r"(a[0]), "r"(a[1]), "r"(a[2]), "r"(a[3]), "r"(b[0]), "r"(b[1]));
}

// ============================================================================
// Deterministic counting sort of tokens by modality (stable).
// ============================================================================
__global__ __launch_bounds__(1024) void sort_tokens(const int* __restrict__ mod)
{
    __shared__ int s[1024];
    const int tid = threadIdx.x;
    int m[4]; int cnt = 0;
#pragma unroll
    for (int u = 0; u < 4; u++) { m[u] = mod[tid*4 + u]; cnt += (m[u] == 0); }
    s[tid] = cnt;
    __syncthreads();
    for (int off = 1; off < 1024; off <<= 1) {
        int v = (tid >= off) ? s[tid - off] : 0;
        __syncthreads();
        s[tid] += v;
        __syncthreads();
    }
    const int c0 = s[1023];
    if (tid == 0) g_c0 = c0;
    int r0 = s[tid] - cnt;
#pragma unroll
    for (int u = 0; u < 4; u++) {
        int g = tid*4 + u;
        if (m[u] == 0) { g_perm[r0] = g; r0++; }
        else           { g_perm[c0 + g - r0] = g; }
    }
}

// ============================================================================
// 3xTF32 mma.sync GEMM over expert-sorted rows. (unchanged from R3)
// ============================================================================
#define MMK_STAGE 32768
#define MM_DSMEM  (2*MMK_STAGE)

__device__ __forceinline__ float ld_a(const char* ap, int m, int k) {
    return *(const float*)(ap + m*128 + ((((k>>2) + m) & 7) << 4) + ((k&3)<<2));
}
__device__ __forceinline__ float ld_b(const char* bp, int k, int n) {
    return *(const float*)(bp + k*512 + ((((n>>2) + 2*k) & 31) << 4) + ((n&3)<<2));
}

__global__ __launch_bounds__(128) void mm_tf32(
    const float* __restrict__ A, const float* __restrict__ W,
    float* __restrict__ C, int K, int NC)
{
    extern __shared__ char sm[];
    __shared__ int sPerm[128];
    const int tid  = threadIdx.x;
    const int lane = tid & 31;
    const int w    = tid >> 5;
    const int wm64 = (w & 1) * 64;
    const int wn64 = (w >> 1) * 64;
    const int bn   = blockIdx.x * 128;
    const int by   = blockIdx.y;

    const int c0 = g_c0;
    const int T0 = (c0 + 127) >> 7;
    const int T1 = (NTOK - c0 + 127) >> 7;
    if (by >= T0 + T1) return;
    const int e       = (by < T0) ? 0 : 1;
    const int rowbase = e ? (c0 + (by - T0) * 128) : (by * 128);
    const int limit   = e ? NTOK : c0;
    const float* Wp   = W + (size_t)e * K * NC;

    if (tid < 128) {
        int gs = rowbase + tid;
        sPerm[tid] = g_perm[gs < NTOK ? gs : (NTOK - 1)];
    }
    __syncthreads();

    const uint32_t sb = smem_u32(sm);

    auto load_chunk = [&](int cc, int p) {
        const uint32_t abase = sb + p * MMK_STAGE;
        const uint32_t bbase = abase + 16384;
        const int k0 = cc * 32;
#pragma unroll
        for (int i = 0; i < 8; i++) {
            int idx = tid + (i << 7);
            int row = idx >> 3, cch = idx & 7;
            const float* src = A + (size_t)sPerm[row] * K + k0 + (cch << 2);
            uint32_t dst = abase + (uint32_t)(row * 128) + ((uint32_t)((cch + row) & 7) << 4);
            CP_ASYNC16(dst, src);
        }
#pragma unroll
        for (int i = 0; i < 8; i++) {
            int idx = tid + (i << 7);
            int row = idx >> 5, cch = idx & 31;
            const float* src = Wp + (size_t)(k0 + row) * NC + bn + (cch << 2);
            uint32_t dst = bbase + (uint32_t)(row * 512) + ((uint32_t)((cch + 2 * row) & 31) << 4);
            CP_ASYNC16(dst, src);
        }
    };

    float acc[4][8][4];
#pragma unroll
    for (int i = 0; i < 4; i++)
#pragma unroll
        for (int j = 0; j < 8; j++)
#pragma unroll
            for (int q = 0; q < 4; q++) acc[i][j][q] = 0.f;

    const int NCH = K / 32;
    load_chunk(0, 0); CP_COMMIT();
    load_chunk(1, 1); CP_COMMIT();

    const int lr = lane >> 2;
    const int lc = lane & 3;

    for (int c = 0; c < NCH; c++) {
        CP_WAIT1();
        __syncthreads();
        const char* ap = sm + (c & 1) * MMK_STAGE;
        const char* bp = ap + 16384;
#pragma unroll
        for (int s = 0; s < 4; s++) {
            uint32_t ah[4][4], al[4][4];
#pragma unroll
            for (int i = 0; i < 4; i++) {
                int m0 = wm64 + i * 16 + lr;
                int kk = s * 8 + lc;
                split_tf32(ld_a(ap, m0,     kk    ), ah[i][0], al[i][0]);
                split_tf32(ld_a(ap, m0 + 8, kk    ), ah[i][1], al[i][1]);
                split_tf32(ld_a(ap, m0,     kk + 4), ah[i][2], al[i][2]);
                split_tf32(ld_a(ap, m0 + 8, kk + 4), ah[i][3], al[i][3]);
            }
            uint32_t bh[8][2], bl[8][2];
#pragma unroll
            for (int j = 0; j < 8; j++) {
                int n  = wn64 + j * 8 + lr;
                int kk = s * 8 + lc;
                split_tf32(ld_b(bp, kk,     n), bh[j][0], bl[j][0]);
                split_tf32(ld_b(bp, kk + 4, n), bh[j][1], bl[j][1]);
            }
#pragma unroll
            for (int i = 0; i < 4; i++)
#pragma unroll
                for (int j = 0; j < 8; j++) {
                    mma1688(acc[i][j], ah[i], bh[j]);
                    mma1688(acc[i][j], al[i], bh[j]);
                    mma1688(acc[i][j], ah[i], bl[j]);
                }
        }
        __syncthreads();
        if (c + 2 < NCH) load_chunk(c + 2, c & 1);
        CP_COMMIT();
    }

#pragma unroll
    for (int i = 0; i < 4; i++) {
        int lr0 = wm64 + i * 16 + lr;
        bool v0 = (rowbase + lr0)     < limit;
        bool v1 = (rowbase + lr0 + 8) < limit;
        int t0 = v0 ? sPerm[lr0]     : 0;
        int t1 = v1 ? sPerm[lr0 + 8] : 0;
#pragma unroll
        for (int j = 0; j < 8; j++) {
            int cb = bn + wn64 + j * 8 + (lc << 1);
            if (v0) *(float2*)&C[(size_t)t0 * NC + cb] = make_float2(acc[i][j][0], acc[i][j][1]);
            if (v1) *(float2*)&C[(size_t)t1 * NC + cb] = make_float2(acc[i][j][2], acc[i][j][3]);
        }
    }
}

// ============================================================================
// Per-head RMSNorm + RoPE, in place.
// ============================================================================
__global__ __launch_bounds__(128) void rmsnorm_rope(
    float* __restrict__ buf, const float* __restrict__ normw,
    const float* __restrict__ fcos, const float* __restrict__ fsin,
    const int* __restrict__ mod, int nheads)
{
    const int n = blockIdx.x;
    const int h = blockIdx.y;
    const int d = threadIdx.x;
    const int s = n & (SEQ_-1);
    const int e = mod[n];
    float* p = buf + (size_t)n*nheads*HD_ + h*HD_;

    float v = p[d];
    float ss = v * v;
#pragma unroll
    for (int o = 16; o > 0; o >>= 1) ss += __shfl_xor_sync(0xffffffffu, ss, o);
    __shared__ float wsum[4];
    if ((d & 31) == 0) wsum[d >> 5] = ss;
    __syncthreads();
    float tot = wsum[0] + wsum[1] + wsum[2] + wsum[3];
    float r = rsqrtf(tot * (1.0f/HD_) + EPS_);
    v = v * r * normw[e*HD_ + d];

    float partner = __shfl_xor_sync(0xffffffffu, v, 1);
    float c  = fcos[s*(HD_/2) + (d >> 1)];
    float sn = fsin[s*(HD_/2) + (d >> 1)];
    float outv = (d & 1) ? fmaf(partner, sn, v * c)
                         : (v * c - partner * sn);
    p[d] = outv;
}

// ============================================================================
// Tensor-core causal flash attention (3xTF32 mma.sync), GQA kv = h>>1.
// CTA: 128 q-rows x one head. 256 threads (8 warps x 16 rows).
// KV tiles of 64. P routed through smem (per-warp-private rows).
// smem: Q 64K | K[2] 32K ea | V[2] 32K ea | P 32K  = 224K
// ============================================================================
#define FA_QOFF 0
#define FA_KOFF 65536
#define FA_VOFF (65536 + 2*32768)
#define FA_POFF (65536 + 4*32768)
#define FA_BYTES (FA_POFF + 32768)

__device__ __forceinline__ float fa_ldq(const char* base, int m, int d) {
    return *(const float*)(base + m*512 + ((((d>>2) + m) & 31) << 4) + ((d&3)<<2));
}
__device__ __forceinline__ float fa_ldk(const char* base, int kv, int d) {
    return *(const float*)(base + kv*512 + ((((d>>2) + kv) & 31) << 4) + ((d&3)<<2));
}
__device__ __forceinline__ float fa_ldv(const char* base, int kv, int d) {
    return *(const float*)(base + kv*512 + ((((d>>2) + 2*kv) & 31) << 4) + ((d&3)<<2));
}
__device__ __forceinline__ char* fa_paddr(char* base, int m, int c) {
    return base + m*256 + ((((c>>2) + m) & 15) << 4) + ((c&3)<<2);
}

__global__ __launch_bounds__(256) void flash_attn(
    const float* __restrict__ Q, const float* __restrict__ Kb,
    const float* __restrict__ Vb, float* __restrict__ O)
{
    extern __shared__ char sm[];
    const int tid  = threadIdx.x;
    const int lane = tid & 31;
    const int w    = tid >> 5;
    const int lr   = lane >> 2;
    const int lc   = lane & 3;

    const int qt = 15 - blockIdx.x;      // big tiles first
    const int h  = blockIdx.y;
    const int b  = blockIdx.z;
    const int kvh   = h >> 1;
    const int qbase = qt * 128;
    const int m0    = w * 16;
    const int niter = 2 * qt + 2;

    const uint32_t sb = smem_u32(sm);

    // ---- issue Q load (group 0) ----
#pragma unroll
    for (int i = 0; i < 16; i++) {
        int idx = tid + (i << 8);        // 0..4095
        int r = idx >> 5, cch = idx & 31;
        const float* src = Q + ((size_t)(b*SEQ_ + qbase + r))*(HQ_*HD_) + h*HD_ + (cch << 2);
        uint32_t dst = sb + FA_QOFF + (uint32_t)(r*512) + ((uint32_t)((cch + r) & 31) << 4);
        CP_ASYNC16(dst, src);
    }
    CP_COMMIT();

    auto load_k = [&](int kt, int p) {
#pragma unroll
        for (int i = 0; i < 8; i++) {
            int idx = tid + (i << 8);    // 0..2047
            int r = idx >> 5, cch = idx & 31;
            const float* src = Kb + ((size_t)(b*SEQ_ + kt*64 + r))*(HK_*HD_) + kvh*HD_ + (cch << 2);
            uint32_t dst = sb + FA_KOFF + (uint32_t)p*32768 + (uint32_t)(r*512)
                         + ((uint32_t)((cch + r) & 31) << 4);
            CP_ASYNC16(dst, src);
        }
        CP_COMMIT();
    };
    auto load_v = [&](int kt, int p) {
#pragma unroll
        for (int i = 0; i < 8; i++) {
            int idx = tid + (i << 8);
            int r = idx >> 5, cch = idx & 31;
            const float* src = Vb + ((size_t)(b*SEQ_ + kt*64 + r))*(HK_*HD_) + kvh*HD_ + (cch << 2);
            uint32_t dst = sb + FA_VOFF + (uint32_t)p*32768 + (uint32_t)(r*512)
                         + ((uint32_t)((cch + 2*r) & 31) << 4);
            CP_ASYNC16(dst, src);
        }
        CP_COMMIT();
    };

    load_k(0, 0);
    load_v(0, 0);

    float o[16][4];
#pragma unroll
    for (int j = 0; j < 16; j++)
#pragma unroll
        for (int q = 0; q < 4; q++) o[j][q] = 0.f;
    float mr0 = -1e30f, mr1 = -1e30f, lr0s = 0.f, lr1s = 0.f;

    const char* qs = sm + FA_QOFF;
    char* ps = sm + FA_POFF;
    const int row0g = qbase + m0 + lr;       // global q row (half 0)

    for (int kt = 0; kt < niter; kt++) {
        const int p = kt & 1;
        cp_wait<1>();                 // K_kt (and Q on first iter) complete
        __syncthreads();              // visibility + buffer protection
        if (kt + 1 < niter) { load_k(kt + 1, p ^ 1); load_v(kt + 1, p ^ 1); }

        const char* ks = sm + FA_KOFF + p*32768;

        // ---- S = Q K^T (3xTF32) ----
        float sa[8][4];
#pragma unroll
        for (int j = 0; j < 8; j++)
#pragma unroll
            for (int q = 0; q < 4; q++) sa[j][q] = 0.f;
#pragma unroll
        for (int s = 0; s < 16; s++) {
            const int kk = s*8 + lc;
            uint32_t ah[4], al[4];
            split_tf32(fa_ldq(qs, m0 + lr,     kk    ), ah[0], al[0]);
            split_tf32(fa_ldq(qs, m0 + 8 + lr, kk    ), ah[1], al[1]);
            split_tf32(fa_ldq(qs, m0 + lr,     kk + 4), ah[2], al[2]);
            split_tf32(fa_ldq(qs, m0 + 8 + lr, kk + 4), ah[3], al[3]);
#pragma unroll
            for (int j = 0; j < 8; j++) {
                uint32_t bh[2], bl[2];
                split_tf32(fa_ldk(ks, j*8 + lr, kk    ), bh[0], bl[0]);
                split_tf32(fa_ldk(ks, j*8 + lr, kk + 4), bh[1], bl[1]);
                mma1688(sa[j], ah, bh);
                mma1688(sa[j], al, bh);
                mma1688(sa[j], ah, bl);
            }
        }

        // ---- softmax (online) ----
        const bool need_mask = (kt >= 2*qt);
        float mx0 = -1e30f, mx1 = -1e30f;
#pragma unroll
        for (int j = 0; j < 8; j++) {
            const int cb = kt*64 + j*8 + 2*lc;
#pragma unroll
            for (int q = 0; q < 4; q++) {
                float v = sa[j][q] * SCALE_;
                if (need_mask) {
                    int col = cb + (q & 1);
                    int row = (q < 2) ? row0g : (row0g + 8);
                    if (col > row) v = -1e30f;
                }
                sa[j][q] = v;
            }
            mx0 = fmaxf(mx0, fmaxf(sa[j][0], sa[j][1]));
            mx1 = fmaxf(mx1, fmaxf(sa[j][2], sa[j][3]));
        }
        mx0 = fmaxf(mx0, __shfl_xor_sync(0xffffffffu, mx0, 1));
        mx0 = fmaxf(mx0, __shfl_xor_sync(0xffffffffu, mx0, 2));
        mx1 = fmaxf(mx1, __shfl_xor_sync(0xffffffffu, mx1, 1));
        mx1 = fmaxf(mx1, __shfl_xor_sync(0xffffffffu, mx1, 2));
        const float mn0 = fmaxf(mr0, mx0);
        const float mn1 = fmaxf(mr1, mx1);
        const float c0 = __expf(mr0 - mn0);
        const float c1 = __expf(mr1 - mn1);
        float ps0 = 0.f, ps1 = 0.f;
#pragma unroll
        for (int j = 0; j < 8; j++) {
            float p0 = __expf(sa[j][0] - mn0);
            float p1 = __expf(sa[j][1] - mn0);
            float p2 = __expf(sa[j][2] - mn1);
            float p3 = __expf(sa[j][3] - mn1);
            ps0 += p0 + p1; ps1 += p2 + p3;
            *(float2*)fa_paddr(ps, m0 + lr,     j*8 + 2*lc) = make_float2(p0, p1);
            *(float2*)fa_paddr(ps, m0 + 8 + lr, j*8 + 2*lc) = make_float2(p2, p3);
        }
        ps0 += __shfl_xor_sync(0xffffffffu, ps0, 1);
        ps0 += __shfl_xor_sync(0xffffffffu, ps0, 2);
        ps1 += __shfl_xor_sync(0xffffffffu, ps1, 1);
        ps1 += __shfl_xor_sync(0xffffffffu, ps1, 2);
        lr0s = lr0s * c0 + ps0;
        lr1s = lr1s * c1 + ps1;
        mr0 = mn0; mr1 = mn1;
#pragma unroll
        for (int j = 0; j < 16; j++) {
            o[j][0] *= c0; o[j][1] *= c0;
            o[j][2] *= c1; o[j][3] *= c1;
        }
        __syncwarp();                  // P visible within warp

        // ---- V ready ----
        if (kt + 1 < niter) cp_wait<2>(); else cp_wait<0>();
        __syncthreads();
        const char* vs = sm + FA_VOFF + p*32768;

        // ---- O += P V (3xTF32) ----
#pragma unroll
        for (int s = 0; s < 8; s++) {
            const int kk = s*8 + lc;
            uint32_t ah[4], al[4];
            split_tf32(*(const float*)fa_paddr(ps, m0 + lr,     kk    ), ah[0], al[0]);
            split_tf32(*(const float*)fa_paddr(ps, m0 + 8 + lr, kk    ), ah[1], al[1]);
            split_tf32(*(const float*)fa_paddr(ps, m0 + lr,     kk + 4), ah[2], al[2]);
            split_tf32(*(const float*)fa_paddr(ps, m0 + 8 + lr, kk + 4), ah[3], al[3]);
#pragma unroll
            for (int j = 0; j < 16; j++) {
                uint32_t bh[2], bl[2];
                split_tf32(fa_ldv(vs, kk,     j*8 + lr), bh[0], bl[0]);
                split_tf32(fa_ldv(vs, kk + 4, j*8 + lr), bh[1], bl[1]);
                mma1688(o[j], ah, bh);
                mma1688(o[j], al, bh);
                mma1688(o[j], ah, bl);
            }
        }
    }

    // ---- normalize + store ----
    const float i0 = 1.f / lr0s;
    const float i1 = 1.f / lr1s;
    const size_t r0 = (size_t)(b*SEQ_ + row0g) * (HQ_*HD_) + h*HD_;
    const size_t r1 = r0 + 8 * (size_t)(HQ_*HD_);
#pragma unroll
    for (int j = 0; j < 16; j++) {
        const int col = j*8 + 2*lc;
        *(float2*)&O[r0 + col] = make_float2(o[j][0]*i0, o[j][1]*i0);
        *(float2*)&O[r1 + col] = make_float2(o[j][2]*i1, o[j][3]*i1);
    }
}

// ============================================================================
// Final per-token RMSNorm over DIM with attn_norm_w[expert]
// ============================================================================
__global__ __launch_bounds__(256) void final_rms(
    const float* __restrict__ in, const float* __restrict__ w,
    const int* __restrict__ mod, float* __restrict__ out)
{
    const int n = blockIdx.x;
    const int tid = threadIdx.x;
    const int e = mod[n];
    const float* row = in + (size_t)n*DIM_;
    float vals[8];
    float ss = 0.f;
#pragma unroll
    for (int u = 0; u < 8; u++) {
        float v = row[tid + u*256];
        vals[u] = v;
        ss += v*v;
    }
#pragma unroll
    for (int o = 16; o > 0; o >>= 1) ss += __shfl_xor_sync(0xffffffffu, ss, o);
    __shared__ float wsum[8];
    if ((tid & 31) == 0) wsum[tid >> 5] = ss;
    __syncthreads();
    float tot = 0.f;
#pragma unroll
    for (int i = 0; i < 8; i++) tot += wsum[i];
    float r = rsqrtf(tot * (1.0f/DIM_) + EPS_);
#pragma unroll
    for (int u = 0; u < 8; u++)
        out[(size_t)n*DIM_ + tid + u*256] = vals[u] * r * w[e*DIM_ + tid + u*256];
}

// ============================================================================
// launch
// ============================================================================
extern "C" void kernel_launch(void* const* d_in, const int* in_sizes, int n_in,
                              void* d_out, int out_size)
{
    const float* x    = (const float*)d_in[0];
    const float* fcos = (const float*)d_in[1];
    const float* fsin = (const float*)d_in[2];
    const float* wq   = (const float*)d_in[3];
    const float* wk   = (const float*)d_in[4];
    const float* wv   = (const float*)d_in[5];
    const float* wo   = (const float*)d_in[6];
    const float* qnw  = (const float*)d_in[7];
    const float* knw  = (const float*)d_in[8];
    const float* anw  = (const float*)d_in[9];
    const int*   mod  = (const int*)d_in[10];
    float* out = (float*)d_out;

    float *pq, *pk, *pv, *pao, *po;
    cudaGetSymbolAddress((void**)&pq,  g_q);
    cudaGetSymbolAddress((void**)&pk,  g_k);
    cudaGetSymbolAddress((void**)&pv,  g_v);
    cudaGetSymbolAddress((void**)&pao, g_ao);
    cudaGetSymbolAddress((void**)&po,  g_o);

    cudaFuncSetAttribute(flash_attn, cudaFuncAttributeMaxDynamicSharedMemorySize, FA_BYTES);
    cudaFuncSetAttribute(mm_tf32,    cudaFuncAttributeMaxDynamicSharedMemorySize, MM_DSMEM);

    // sort tokens by expert (deterministic)
    sort_tokens<<<1, 1024>>>(mod);

    // QKV projections (expert-sorted, mma.sync 3xTF32)
    mm_tf32<<<dim3(16, 33), 128, MM_DSMEM>>>(x, wq, pq, DIM_, HQ_*HD_);
    mm_tf32<<<dim3( 8, 33), 128, MM_DSMEM>>>(x, wk, pk, DIM_, HK_*HD_);
    mm_tf32<<<dim3( 8, 33), 128, MM_DSMEM>>>(x, wv, pv, DIM_, HK_*HD_);

    // per-head rmsnorm + rope (norm BEFORE rope)
    rmsnorm_rope<<<dim3(NTOK, HQ_), 128>>>(pq, qnw, fcos, fsin, mod, HQ_);
    rmsnorm_rope<<<dim3(NTOK, HK_), 128>>>(pk, knw, fcos, fsin, mod, HK_);

    // tensor-core causal flash attention
    flash_attn<<<dim3(16, 16, 2), 256, FA_BYTES>>>(pq, pk, pv, pao);

    // output projection + final rmsnorm
    mm_tf32<<<dim3(16, 33), 128, MM_DSMEM>>>(pao, wo, po, HQ_*HD_, DIM_);
    final_rms<<<NTOK, 256>>>(po, anw, mod, out);
}

// round 5
// speedup vs baseline: 5.9137x; 1.7380x over previous
#include <cuda_runtime.h>
#include <cuda_bf16.h>
#include <math.h>
#include <cstdint>

// ---------------- problem constants ----------------
#define E_   2
#define HQ_  16
#define HK_  8
#define HD_  128
#define DIM_ 2048
#define BS_  2
#define SEQ_ 2048
#define NTOK (BS_*SEQ_)          // 4096
#define EPS_ 1e-6f
#define SCALE_ 0.08838834764831845f   // 1/sqrt(128)

typedef __nv_bfloat16 bf16;

// ---------------- scratch (device globals) ----------------
__device__ float g_q [NTOK * (HQ_*HD_)];
__device__ float g_k [NTOK * (HK_*HD_)];
__device__ float g_v [NTOK * (HK_*HD_)];
__device__ float g_o [NTOK * DIM_];
__device__ int   g_perm[NTOK];
__device__ int   g_c0;

// bf16 split buffers
__device__ bf16 g_xh [NTOK*DIM_],      g_xl [NTOK*DIM_];
__device__ bf16 g_wqh[E_*DIM_*HQ_*HD_], g_wql[E_*DIM_*HQ_*HD_];
__device__ bf16 g_wkh[E_*DIM_*HK_*HD_], g_wkl[E_*DIM_*HK_*HD_];
__device__ bf16 g_wvh[E_*DIM_*HK_*HD_], g_wvl[E_*DIM_*HK_*HD_];
__device__ bf16 g_woh[E_*DIM_*HQ_*HD_], g_wol[E_*DIM_*HQ_*HD_];
__device__ bf16 g_qh [NTOK*(HQ_*HD_)],  g_ql [NTOK*(HQ_*HD_)];
__device__ bf16 g_kh [NTOK*(HK_*HD_)],  g_kl [NTOK*(HK_*HD_)];
__device__ bf16 g_vth[NTOK*(HK_*HD_)],  g_vtl[NTOK*(HK_*HD_)];   // [b][kvh][d][seq]
__device__ bf16 g_aoh[NTOK*(HQ_*HD_)],  g_aol[NTOK*(HQ_*HD_)];

// =============================== helpers ===============================
__device__ __forceinline__ uint32_t smem_u32(const void* p) {
    uint32_t a;
    asm("{ .reg .u64 t; cvta.to.shared.u64 t, %1; cvt.u32.u64 %0, t; }" : "=r"(a) : "l"(p));
    return a;
}
#define CP_ASYNC16(dst, src) \
    asm volatile("cp.async.cg.shared.global [%0], [%1], 16;" :: "r"(dst), "l"(src) : "memory")
#define CP_COMMIT() asm volatile("cp.async.commit_group;" ::: "memory")
template<int N> __device__ __forceinline__ void cp_wait() {
    asm volatile("cp.async.wait_group %0;" :: "n"(N) : "memory");
}

__device__ __forceinline__ void bsplit(float x, uint16_t& h, uint16_t& l) {
    bf16 bh = __float2bfloat16_rn(x);
    h = __bfloat16_as_ushort(bh);
    l = __bfloat16_as_ushort(__float2bfloat16_rn(x - __bfloat162float(bh)));
}
__device__ __forceinline__ uint32_t packb(uint16_t lo_elem, uint16_t hi_elem) {
    return (uint32_t)lo_elem | ((uint32_t)hi_elem << 16);
}
__device__ __forceinline__ void mma16816(float* c, const uint32_t* a, const uint32_t* b) {
    asm volatile("mma.sync.aligned.m16n8k16.row.col.f32.bf16.bf16.f32 "
        "{%0,%1,%2,%3}, {%4,%5,%6,%7}, {%8,%9}, {%0,%1,%2,%3};"
        : "+f"(c[0]), "+f"(c[1]), "+f"(c[2]), "+f"(c[3])
        : "r"(a[0]), "r"(a[1]), "r"(a[2]), "r"(a[3]), "r"(b[0]), "r"(b[1]));
}
// 16B-chunk XOR swizzles (conflict-free frag reads; see analysis)
__device__ __forceinline__ uint32_t sw256(int r, int off) {
    return (uint32_t)(r*256 + (off ^ ((r & 7) << 4)));
}
__device__ __forceinline__ uint32_t sw128(int r, int off) {
    return (uint32_t)(r*128 + (off ^ ((r & 7) << 4)));
}

// ============================================================================
// sort tokens by modality (stable counting sort), deterministic
// ============================================================================
__global__ __launch_bounds__(1024) void sort_tokens(const int* __restrict__ mod)
{
    __shared__ int s[1024];
    const int tid = threadIdx.x;
    int m[4]; int cnt = 0;
#pragma unroll
    for (int u = 0; u < 4; u++) { m[u] = mod[tid*4 + u]; cnt += (m[u] == 0); }
    s[tid] = cnt;
    __syncthreads();
    for (int off = 1; off < 1024; off <<= 1) {
        int v = (tid >= off) ? s[tid - off] : 0;
        __syncthreads();
        s[tid] += v;
        __syncthreads();
    }
    const int c0 = s[1023];
    if (tid == 0) g_c0 = c0;
    int r0 = s[tid] - cnt;
#pragma unroll
    for (int u = 0; u < 4; u++) {
        int g = tid*4 + u;
        if (m[u] == 0) { g_perm[r0] = g; r0++; }
        else           { g_perm[c0 + g - r0] = g; }
    }
}

// ============================================================================
// elementwise fp32 -> bf16 hi/lo split (for x)
// ============================================================================
__global__ __launch_bounds__(256) void split_f32(
    const float* __restrict__ in, bf16* __restrict__ hi, bf16* __restrict__ lo, int n4)
{
    int i = blockIdx.x * 256 + threadIdx.x;
    if (i >= n4) return;
    float4 v = ((const float4*)in)[i];
    uint16_t hx,lx,hy,ly,hz,lz,hw,lw;
    bsplit(v.x,hx,lx); bsplit(v.y,hy,ly); bsplit(v.z,hz,lz); bsplit(v.w,hw,lw);
    ((uint2*)hi)[i] = make_uint2(packb(hx,hy), packb(hz,hw));
    ((uint2*)lo)[i] = make_uint2(packb(lx,ly), packb(lz,lw));
}

// ============================================================================
// weight transpose-split: W [e][K][NC] fp32 -> T [e][NC][K] bf16 hi/lo
// ============================================================================
__global__ __launch_bounds__(256) void wtrans_split(
    const float* __restrict__ W, bf16* __restrict__ Th, bf16* __restrict__ Tl,
    int K, int NC)
{
    __shared__ float t[32][33];
    const int e  = blockIdx.z;
    const int k0 = blockIdx.x * 32, n0 = blockIdx.y * 32;
    const int tx = threadIdx.x & 31, ty = threadIdx.x >> 5;
    const float* Wp = W + (size_t)e * K * NC;
    for (int r = ty; r < 32; r += 8)
        t[r][tx] = Wp[(size_t)(k0 + r) * NC + n0 + tx];
    __syncthreads();
    bf16* th = Th + (size_t)e * NC * K;
    bf16* tl = Tl + (size_t)e * NC * K;
    for (int r = ty; r < 32; r += 8) {
        float v = t[tx][r];
        uint16_t h, l; bsplit(v, h, l);
        size_t o = (size_t)(n0 + r) * K + k0 + tx;
        th[o] = __ushort_as_bfloat16(h);
        tl[o] = __ushort_as_bfloat16(l);
    }
}

// ============================================================================
// V transpose-split: g_v fp32 [b*2048+s][kvh*128+d] -> Vt [b][kvh][d][seq] hi/lo
// ============================================================================
__global__ __launch_bounds__(256) void vtrans_split(
    const float* __restrict__ V, bf16* __restrict__ Th, bf16* __restrict__ Tl)
{
    __shared__ float t[32][33];
    const int s0 = blockIdx.x * 32, d0 = blockIdx.y * 32;
    const int z  = blockIdx.z;                 // b*8 + kvh
    const int b  = z >> 3, kvh = z & 7;
    const int tx = threadIdx.x & 31, ty = threadIdx.x >> 5;
    for (int r = ty; r < 32; r += 8)
        t[r][tx] = V[(size_t)(b*SEQ_ + s0 + r) * (HK_*HD_) + kvh*HD_ + d0 + tx];
    __syncthreads();
    for (int r = ty; r < 32; r += 8) {
        float v = t[tx][r];
        uint16_t h, l; bsplit(v, h, l);
        size_t o = (size_t)(z*HD_ + d0 + r) * SEQ_ + s0 + tx;
        Th[o] = __ushort_as_bfloat16(h);
        Tl[o] = __ushort_as_bfloat16(l);
    }
}

// ============================================================================
// bf16x2 mma.sync GEMM over expert-sorted rows.
// C[perm[p]][c] = sum_k A[perm[p]][k] * W[e(p)][k][c]
// A hi/lo bf16 [n][K]; B = Wt hi/lo bf16 [e][NC][K] (k contiguous).
// Tile 128x128, BK=32, 128 threads (4 warps, 64x64 each), cp.async 2-stage.
// smem rows padded to 80B -> conflict-free frag reads.
// ============================================================================
#define MM_STAGE 40960          // Ah 10240 | Al | Bh | Bl
#define MM_DSMEM (2*MM_STAGE)

__global__ __launch_bounds__(128) void mm_bf16(
    const bf16* __restrict__ Ah, const bf16* __restrict__ Al,
    const bf16* __restrict__ Bh, const bf16* __restrict__ Bl,
    float* __restrict__ C, int K, int NC)
{
    extern __shared__ char sm[];
    __shared__ int sPerm[128];
    const int tid  = threadIdx.x;
    const int lane = tid & 31;
    const int w    = tid >> 5;
    const int wm64 = (w & 1) * 64;
    const int wn64 = (w >> 1) * 64;
    const int bn   = blockIdx.x * 128;
    const int by   = blockIdx.y;

    const int c0 = g_c0;
    const int T0 = (c0 + 127) >> 7;
    const int T1 = (NTOK - c0 + 127) >> 7;
    if (by >= T0 + T1) return;
    const int e       = (by < T0) ? 0 : 1;
    const int rowbase = e ? (c0 + (by - T0) * 128) : (by * 128);
    const int limit   = e ? NTOK : c0;
    const size_t bofs = (size_t)e * NC * K + (size_t)bn * K;

    {
        int gs = rowbase + tid;
        sPerm[tid] = g_perm[gs < NTOK ? gs : (NTOK - 1)];
    }
    __syncthreads();

    const uint32_t sb = smem_u32(sm);

    auto load_chunk = [&](int cc, int p) {
        const int k0 = cc * 32;
        const uint32_t base = sb + p * MM_STAGE;
#pragma unroll
        for (int i = 0; i < 8; i++) {          // A: 1024 16B chunks (hi+lo)
            int idx = tid + (i << 7);
            int comp = idx >> 9, rem = idx & 511;
            int r = rem >> 2, c = rem & 3;
            const bf16* src = (comp ? Al : Ah) + (size_t)sPerm[r] * K + k0 + c * 8;
            CP_ASYNC16(base + comp*10240 + (uint32_t)(r*80 + c*16), src);
        }
#pragma unroll
        for (int i = 0; i < 8; i++) {          // B: 1024 16B chunks (hi+lo)
            int idx = tid + (i << 7);
            int comp = idx >> 9, rem = idx & 511;
            int r = rem >> 2, c = rem & 3;
            const bf16* src = (comp ? Bl : Bh) + bofs + (size_t)r * K + k0 + c * 8;
            CP_ASYNC16(base + 20480 + comp*10240 + (uint32_t)(r*80 + c*16), src);
        }
    };

    float acc[4][8][4];
#pragma unroll
    for (int i = 0; i < 4; i++)
#pragma unroll
        for (int j = 0; j < 8; j++)
#pragma unroll
            for (int q = 0; q < 4; q++) acc[i][j][q] = 0.f;

    const int NCH = K / 32;
    load_chunk(0, 0); CP_COMMIT();
    load_chunk(1, 1); CP_COMMIT();

    const int lr = lane >> 2;
    const int lc = lane & 3;

    for (int c = 0; c < NCH; c++) {
        cp_wait<1>();
        __syncthreads();
        const char* ah_s = sm + (c & 1) * MM_STAGE;
        const char* al_s = ah_s + 10240;
        const char* bh_s = ah_s + 20480;
        const char* bl_s = ah_s + 30720;
#pragma unroll
        for (int ks = 0; ks < 2; ks++) {
            const int b0 = ks * 32 + lc * 4;
            uint32_t fah[4][4], fal[4][4];
#pragma unroll
            for (int i = 0; i < 4; i++) {
                int m = wm64 + i * 16 + lr;
                fah[i][0] = *(const uint32_t*)(ah_s + m*80 + b0);
                fah[i][1] = *(const uint32_t*)(ah_s + (m+8)*80 + b0);
                fah[i][2] = *(const uint32_t*)(ah_s + m*80 + b0 + 16);
                fah[i][3] = *(const uint32_t*)(ah_s + (m+8)*80 + b0 + 16);
                fal[i][0] = *(const uint32_t*)(al_s + m*80 + b0);
                fal[i][1] = *(const uint32_t*)(al_s + (m+8)*80 + b0);
                fal[i][2] = *(const uint32_t*)(al_s + m*80 + b0 + 16);
                fal[i][3] = *(const uint32_t*)(al_s + (m+8)*80 + b0 + 16);
            }
#pragma unroll
            for (int j = 0; j < 8; j++) {
                int n = wn64 + j * 8 + lr;
                uint32_t fbh[2], fbl[2];
                fbh[0] = *(const uint32_t*)(bh_s + n*80 + b0);
                fbh[1] = *(const uint32_t*)(bh_s + n*80 + b0 + 16);
                fbl[0] = *(const uint32_t*)(bl_s + n*80 + b0);
                fbl[1] = *(const uint32_t*)(bl_s + n*80 + b0 + 16);
#pragma unroll
                for (int i = 0; i < 4; i++) {
                    mma16816(acc[i][j], fah[i], fbh);
                    mma16816(acc[i][j], fal[i], fbh);
                    mma16816(acc[i][j], fah[i], fbl);
                }
            }
        }
        __syncthreads();
        if (c + 2 < NCH) load_chunk(c + 2, c & 1);
        CP_COMMIT();
    }

    // epilogue: scatter back to token order (fp32)
#pragma unroll
    for (int i = 0; i < 4; i++) {
        int lr0 = wm64 + i * 16 + lr;
        bool v0 = (rowbase + lr0)     < limit;
        bool v1 = (rowbase + lr0 + 8) < limit;
        int t0 = v0 ? sPerm[lr0]     : 0;
        int t1 = v1 ? sPerm[lr0 + 8] : 0;
#pragma unroll
        for (int j = 0; j < 8; j++) {
            int cb = bn + wn64 + j * 8 + (lc << 1);
            if (v0) *(float2*)&C[(size_t)t0 * NC + cb] = make_float2(acc[i][j][0], acc[i][j][1]);
            if (v1) *(float2*)&C[(size_t)t1 * NC + cb] = make_float2(acc[i][j][2], acc[i][j][3]);
        }
    }
}

// ============================================================================
// Per-head RMSNorm + RoPE, fp32 in -> bf16 hi/lo out
// ============================================================================
__global__ __launch_bounds__(128) void rmsnorm_rope_split(
    const float* __restrict__ buf, const float* __restrict__ normw,
    const float* __restrict__ fcos, const float* __restrict__ fsin,
    const int* __restrict__ mod, int nheads,
    bf16* __restrict__ ohi, bf16* __restrict__ olo)
{
    const int n = blockIdx.x;
    const int h = blockIdx.y;
    const int d = threadIdx.x;
    const int s = n & (SEQ_-1);
    const int e = mod[n];
    const size_t base = (size_t)n*nheads*HD_ + h*HD_;

    float v = buf[base + d];
    float ss = v * v;
#pragma unroll
    for (int o = 16; o > 0; o >>= 1) ss += __shfl_xor_sync(0xffffffffu, ss, o);
    __shared__ float wsum[4];
    if ((d & 31) == 0) wsum[d >> 5] = ss;
    __syncthreads();
    float tot = wsum[0] + wsum[1] + wsum[2] + wsum[3];
    float r = rsqrtf(tot * (1.0f/HD_) + EPS_);
    v = v * r * normw[e*HD_ + d];

    float partner = __shfl_xor_sync(0xffffffffu, v, 1);
    float c  = fcos[s*(HD_/2) + (d >> 1)];
    float sn = fsin[s*(HD_/2) + (d >> 1)];
    float outv = (d & 1) ? fmaf(partner, sn, v * c)
                         : (v * c - partner * sn);
    uint16_t hh, ll; bsplit(outv, hh, ll);
    ohi[base + d] = __ushort_as_bfloat16(hh);
    olo[base + d] = __ushort_as_bfloat16(ll);
}

// ============================================================================
// Tensor-core causal flash attention (bf16x2), GQA kv = h>>1.
// CTA: 128 q-rows x one head, 256 threads (8 warps x 16 rows), kv tiles 64.
// smem: Qh 32K | Ql 32K | K[2] (h16+l16) | Vt[2] (h16+l16) | Ph 16K | Pl 16K
// ============================================================================
#define FQ_H 0
#define FQ_L 32768
#define FK(p) (65536  + (p)*32768)
#define FV(p) (131072 + (p)*32768)
#define FP_H 196608
#define FP_L 212992
#define FA_BYTES 229376

__global__ __launch_bounds__(256) void flash_attn(
    const bf16* __restrict__ Qh, const bf16* __restrict__ Ql,
    const bf16* __restrict__ Kh, const bf16* __restrict__ Kl,
    const bf16* __restrict__ Vth, const bf16* __restrict__ Vtl,
    bf16* __restrict__ AOh, bf16* __restrict__ AOl)
{
    extern __shared__ char sm[];
    const int tid  = threadIdx.x;
    const int lane = tid & 31;
    const int w    = tid >> 5;
    const int lr   = lane >> 2;
    const int lc   = lane & 3;

    const int qt = 15 - blockIdx.x;      // big tiles first
    const int h  = blockIdx.y;
    const int b  = blockIdx.z;
    const int kvh   = h >> 1;
    const int qbase = qt * 128;
    const int m0    = w * 16;
    const int niter = 2 * qt + 2;

    const uint32_t sb = smem_u32(sm);

    // ---- Q load (hi+lo): 4096 16B chunks ----
#pragma unroll
    for (int i = 0; i < 16; i++) {
        int idx = tid + (i << 8);
        int comp = idx >> 11, rem = idx & 2047;
        int r = rem >> 4, c = rem & 15;
        const bf16* src = (comp ? Ql : Qh)
            + (size_t)(b*SEQ_ + qbase + r)*(HQ_*HD_) + h*HD_ + c*8;
        CP_ASYNC16(sb + (comp ? FQ_L : FQ_H) + sw256(r, c*16), src);
    }
    CP_COMMIT();

    auto load_k = [&](int kt, int p) {
#pragma unroll
        for (int i = 0; i < 8; i++) {
            int idx = tid + (i << 8);
            int comp = idx >> 10, rem = idx & 1023;
            int r = rem >> 4, c = rem & 15;
            const bf16* src = (comp ? Kl : Kh)
                + (size_t)(b*SEQ_ + kt*64 + r)*(HK_*HD_) + kvh*HD_ + c*8;
            CP_ASYNC16(sb + FK(p) + comp*16384 + sw256(r, c*16), src);
        }
        CP_COMMIT();
    };
    auto load_v = [&](int kt, int p) {
#pragma unroll
        for (int i = 0; i < 8; i++) {
            int idx = tid + (i << 8);
            int comp = idx >> 10, rem = idx & 1023;
            int r = rem >> 3, c = rem & 7;       // 128 d-rows x 8 chunks
            const bf16* src = (comp ? Vtl : Vth)
                + (size_t)((b*HK_ + kvh)*HD_ + r)*SEQ_ + kt*64 + c*8;
            CP_ASYNC16(sb + FV(p) + comp*16384 + sw128(r, c*16), src);
        }
        CP_COMMIT();
    };

    load_k(0, 0);
    load_v(0, 0);

    float o[16][4];
#pragma unroll
    for (int j = 0; j < 16; j++)
#pragma unroll
        for (int q = 0; q < 4; q++) o[j][q] = 0.f;
    float mr0 = -1e30f, mr1 = -1e30f, lr0s = 0.f, lr1s = 0.f;

    const int row0g = qbase + m0 + lr;

    for (int kt = 0; kt < niter; kt++) {
        const int p = kt & 1;
        cp_wait<1>();
        __syncthreads();
        if (kt + 1 < niter) { load_k(kt + 1, p ^ 1); load_v(kt + 1, p ^ 1); }

        const char* kh_s = sm + FK(p);
        const char* kl_s = kh_s + 16384;
        const char* qh_s = sm + FQ_H;
        const char* ql_s = sm + FQ_L;

        // ---- S = Q K^T (bf16x2) ----
        float sa[8][4];
#pragma unroll
        for (int j = 0; j < 8; j++)
#pragma unroll
            for (int q = 0; q < 4; q++) sa[j][q] = 0.f;
#pragma unroll
        for (int s = 0; s < 8; s++) {
            const int b0 = s*32 + lc*4;
            uint32_t fqh[4], fql[4];
            fqh[0] = *(const uint32_t*)(qh_s + sw256(m0 + lr,     b0));
            fqh[1] = *(const uint32_t*)(qh_s + sw256(m0 + 8 + lr, b0));
            fqh[2] = *(const uint32_t*)(qh_s + sw256(m0 + lr,     b0 + 16));
            fqh[3] = *(const uint32_t*)(qh_s + sw256(m0 + 8 + lr, b0 + 16));
            fql[0] = *(const uint32_t*)(ql_s + sw256(m0 + lr,     b0));
            fql[1] = *(const uint32_t*)(ql_s + sw256(m0 + 8 + lr, b0));
            fql[2] = *(const uint32_t*)(ql_s + sw256(m0 + lr,     b0 + 16));
            fql[3] = *(const uint32_t*)(ql_s + sw256(m0 + 8 + lr, b0 + 16));
#pragma unroll
            for (int j = 0; j < 8; j++) {
                const int n = j*8 + lr;
                uint32_t fkh[2], fkl[2];
                fkh[0] = *(const uint32_t*)(kh_s + sw256(n, b0));
                fkh[1] = *(const uint32_t*)(kh_s + sw256(n, b0 + 16));
                fkl[0] = *(const uint32_t*)(kl_s + sw256(n, b0));
                fkl[1] = *(const uint32_t*)(kl_s + sw256(n, b0 + 16));
                mma16816(sa[j], fqh, fkh);
                mma16816(sa[j], fql, fkh);
                mma16816(sa[j], fqh, fkl);
            }
        }

        // ---- online softmax ----
        const bool need_mask = (kt >= 2*qt);
        float mx0 = -1e30f, mx1 = -1e30f;
#pragma unroll
        for (int j = 0; j < 8; j++) {
            const int cb = kt*64 + j*8 + 2*lc;
#pragma unroll
            for (int q = 0; q < 4; q++) {
                float v = sa[j][q] * SCALE_;
                if (need_mask) {
                    int col = cb + (q & 1);
                    int row = (q < 2) ? row0g : (row0g + 8);
                    if (col > row) v = -1e30f;
                }
                sa[j][q] = v;
            }
            mx0 = fmaxf(mx0, fmaxf(sa[j][0], sa[j][1]));
            mx1 = fmaxf(mx1, fmaxf(sa[j][2], sa[j][3]));
        }
        mx0 = fmaxf(mx0, __shfl_xor_sync(0xffffffffu, mx0, 1));
        mx0 = fmaxf(mx0, __shfl_xor_sync(0xffffffffu, mx0, 2));
        mx1 = fmaxf(mx1, __shfl_xor_sync(0xffffffffu, mx1, 1));
        mx1 = fmaxf(mx1, __shfl_xor_sync(0xffffffffu, mx1, 2));
        const float mn0 = fmaxf(mr0, mx0);
        const float mn1 = fmaxf(mr1, mx1);
        const float c0 = __expf(mr0 - mn0);
        const float c1 = __expf(mr1 - mn1);
        float ps0 = 0.f, ps1 = 0.f;
        char* ph_s = sm + FP_H;
        char* pl_s = sm + FP_L;
#pragma unroll
        for (int j = 0; j < 8; j++) {
            float p0 = __expf(sa[j][0] - mn0);
            float p1 = __expf(sa[j][1] - mn0);
            float p2 = __expf(sa[j][2] - mn1);
            float p3 = __expf(sa[j][3] - mn1);
            ps0 += p0 + p1; ps1 += p2 + p3;
            uint16_t h0,l0,h1,l1,h2,l2,h3,l3;
            bsplit(p0,h0,l0); bsplit(p1,h1,l1); bsplit(p2,h2,l2); bsplit(p3,h3,l3);
            const int cb = j*16 + lc*4;
            *(uint32_t*)(ph_s + sw128(m0 + lr,     cb)) = packb(h0, h1);
            *(uint32_t*)(ph_s + sw128(m0 + 8 + lr, cb)) = packb(h2, h3);
            *(uint32_t*)(pl_s + sw128(m0 + lr,     cb)) = packb(l0, l1);
            *(uint32_t*)(pl_s + sw128(m0 + 8 + lr, cb)) = packb(l2, l3);
        }
        ps0 += __shfl_xor_sync(0xffffffffu, ps0, 1);
        ps0 += __shfl_xor_sync(0xffffffffu, ps0, 2);
        ps1 += __shfl_xor_sync(0xffffffffu, ps1, 1);
        ps1 += __shfl_xor_sync(0xffffffffu, ps1, 2);
        lr0s = lr0s * c0 + ps0;
        lr1s = lr1s * c1 + ps1;
        mr0 = mn0; mr1 = mn1;
#pragma unroll
        for (int j = 0; j < 16; j++) {
            o[j][0] *= c0; o[j][1] *= c0;
            o[j][2] *= c1; o[j][3] *= c1;
        }
        __syncwarp();

        // ---- V ready ----
        if (kt + 1 < niter) cp_wait<2>(); else cp_wait<0>();
        __syncthreads();
        const char* vh_s = sm + FV(p);
        const char* vl_s = vh_s + 16384;

        // ---- O += P V (bf16x2) ----
#pragma unroll
        for (int s = 0; s < 4; s++) {
            const int b0 = s*32 + lc*4;
            uint32_t fph[4], fpl[4];
            fph[0] = *(const uint32_t*)(ph_s + sw128(m0 + lr,     b0));
            fph[1] = *(const uint32_t*)(ph_s + sw128(m0 + 8 + lr, b0));
            fph[2] = *(const uint32_t*)(ph_s + sw128(m0 + lr,     b0 + 16));
            fph[3] = *(const uint32_t*)(ph_s + sw128(m0 + 8 + lr, b0 + 16));
            fpl[0] = *(const uint32_t*)(pl_s + sw128(m0 + lr,     b0));
            fpl[1] = *(const uint32_t*)(pl_s + sw128(m0 + 8 + lr, b0));
            fpl[2] = *(const uint32_t*)(pl_s + sw128(m0 + lr,     b0 + 16));
            fpl[3] = *(const uint32_t*)(pl_s + sw128(m0 + 8 + lr, b0 + 16));
#pragma unroll
            for (int j = 0; j < 16; j++) {
                const int n = j*8 + lr;
                uint32_t fvh[2], fvl[2];
                fvh[0] = *(const uint32_t*)(vh_s + sw128(n, b0));
                fvh[1] = *(const uint32_t*)(vh_s + sw128(n, b0 + 16));
                fvl[0] = *(const uint32_t*)(vl_s + sw128(n, b0));
                fvl[1] = *(const uint32_t*)(vl_s + sw128(n, b0 + 16));
                mma16816(o[j], fph, fvh);
                mma16816(o[j], fpl, fvh);
                mma16816(o[j], fph, fvl);
            }
        }
    }

    // ---- normalize + split-store AO ----
    const float i0 = 1.f / lr0s;
    const float i1 = 1.f / lr1s;
    const size_t t0 = (size_t)(b*SEQ_ + row0g);
    const size_t t1 = t0 + 8;
#pragma unroll
    for (int j = 0; j < 16; j++) {
        const int col = h*HD_ + j*8 + 2*lc;
        uint16_t h0,l0,h1,l1;
        bsplit(o[j][0]*i0, h0, l0); bsplit(o[j][1]*i0, h1, l1);
        size_t off0 = t0*(HQ_*HD_) + col;
        *(uint32_t*)((char*)AOh + 2*off0) = packb(h0, h1);
        *(uint32_t*)((char*)AOl + 2*off0) = packb(l0, l1);
        bsplit(o[j][2]*i1, h0, l0); bsplit(o[j][3]*i1, h1, l1);
        size_t off1 = t1*(HQ_*HD_) + col;
        *(uint32_t*)((char*)AOh + 2*off1) = packb(h0, h1);
        *(uint32_t*)((char*)AOl + 2*off1) = packb(l0, l1);
    }
}

// ============================================================================
// Final per-token RMSNorm over DIM with attn_norm_w[expert]
// ============================================================================
__global__ __launch_bounds__(256) void final_rms(
    const float* __restrict__ in, const float* __restrict__ w,
    const int* __restrict__ mod, float* __restrict__ out)
{
    const int n = blockIdx.x;
    const int tid = threadIdx.x;
    const int e = mod[n];
    const float* row = in + (size_t)n*DIM_;
    float vals[8];
    float ss = 0.f;
#pragma unroll
    for (int u = 0; u < 8; u++) {
        float v = row[tid + u*256];
        vals[u] = v;
        ss += v*v;
    }
#pragma unroll
    for (int o = 16; o > 0; o >>= 1) ss += __shfl_xor_sync(0xffffffffu, ss, o);
    __shared__ float wsum[8];
    if ((tid & 31) == 0) wsum[tid >> 5] = ss;
    __syncthreads();
    float tot = 0.f;
#pragma unroll
    for (int i = 0; i < 8; i++) tot += wsum[i];
    float r = rsqrtf(tot * (1.0f/DIM_) + EPS_);
#pragma unroll
    for (int u = 0; u < 8; u++)
        out[(size_t)n*DIM_ + tid + u*256] = vals[u] * r * w[e*DIM_ + tid + u*256];
}

// ============================================================================
// launch
// ============================================================================
extern "C" void kernel_launch(void* const* d_in, const int* in_sizes, int n_in,
                              void* d_out, int out_size)
{
    const float* x    = (const float*)d_in[0];
    const float* fcos = (const float*)d_in[1];
    const float* fsin = (const float*)d_in[2];
    const float* wq   = (const float*)d_in[3];
    const float* wk   = (const float*)d_in[4];
    const float* wv   = (const float*)d_in[5];
    const float* wo   = (const float*)d_in[6];
    const float* qnw  = (const float*)d_in[7];
    const float* knw  = (const float*)d_in[8];
    const float* anw  = (const float*)d_in[9];
    const int*   mod  = (const int*)d_in[10];
    float* out = (float*)d_out;

    float *pq, *pk, *pv, *po;
    bf16 *pxh, *pxl, *pwqh, *pwql, *pwkh, *pwkl, *pwvh, *pwvl, *pwoh, *pwol;
    bf16 *pqh, *pql, *pkh, *pkl, *pvth, *pvtl, *paoh, *paol;
    cudaGetSymbolAddress((void**)&pq,  g_q);
    cudaGetSymbolAddress((void**)&pk,  g_k);
    cudaGetSymbolAddress((void**)&pv,  g_v);
    cudaGetSymbolAddress((void**)&po,  g_o);
    cudaGetSymbolAddress((void**)&pxh, g_xh);  cudaGetSymbolAddress((void**)&pxl, g_xl);
    cudaGetSymbolAddress((void**)&pwqh, g_wqh); cudaGetSymbolAddress((void**)&pwql, g_wql);
    cudaGetSymbolAddress((void**)&pwkh, g_wkh); cudaGetSymbolAddress((void**)&pwkl, g_wkl);
    cudaGetSymbolAddress((void**)&pwvh, g_wvh); cudaGetSymbolAddress((void**)&pwvl, g_wvl);
    cudaGetSymbolAddress((void**)&pwoh, g_woh); cudaGetSymbolAddress((void**)&pwol, g_wol);
    cudaGetSymbolAddress((void**)&pqh, g_qh);   cudaGetSymbolAddress((void**)&pql, g_ql);
    cudaGetSymbolAddress((void**)&pkh, g_kh);   cudaGetSymbolAddress((void**)&pkl, g_kl);
    cudaGetSymbolAddress((void**)&pvth, g_vth); cudaGetSymbolAddress((void**)&pvtl, g_vtl);
    cudaGetSymbolAddress((void**)&paoh, g_aoh); cudaGetSymbolAddress((void**)&paol, g_aol);

    cudaFuncSetAttribute(flash_attn, cudaFuncAttributeMaxDynamicSharedMemorySize, FA_BYTES);
    cudaFuncSetAttribute(mm_bf16,    cudaFuncAttributeMaxDynamicSharedMemorySize, MM_DSMEM);

    // preprocessing
    sort_tokens<<<1, 1024>>>(mod);
    split_f32<<<(NTOK*DIM_/4 + 255)/256, 256>>>(x, pxh, pxl, NTOK*DIM_/4);
    wtrans_split<<<dim3(64, 64, 2), 256>>>(wq, pwqh, pwql, DIM_, HQ_*HD_);
    wtrans_split<<<dim3(64, 32, 2), 256>>>(wk, pwkh, pwkl, DIM_, HK_*HD_);
    wtrans_split<<<dim3(64, 32, 2), 256>>>(wv, pwvh, pwvl, DIM_, HK_*HD_);
    wtrans_split<<<dim3(64, 64, 2), 256>>>(wo, pwoh, pwol, HQ_*HD_, DIM_);

    // QKV projections
    mm_bf16<<<dim3(16, 33), 128, MM_DSMEM>>>(pxh, pxl, pwqh, pwql, pq, DIM_, HQ_*HD_);
    mm_bf16<<<dim3( 8, 33), 128, MM_DSMEM>>>(pxh, pxl, pwkh, pwkl, pk, DIM_, HK_*HD_);
    mm_bf16<<<dim3( 8, 33), 128, MM_DSMEM>>>(pxh, pxl, pwvh, pwvl, pv, DIM_, HK_*HD_);

    // rmsnorm + rope -> bf16 splits; V transpose-split
    rmsnorm_rope_split<<<dim3(NTOK, HQ_), 128>>>(pq, qnw, fcos, fsin, mod, HQ_, pqh, pql);
    rmsnorm_rope_split<<<dim3(NTOK, HK_), 128>>>(pk, knw, fcos, fsin, mod, HK_, pkh, pkl);
    vtrans_split<<<dim3(64, 4, 16), 256>>>(pv, pvth, pvtl);

    // attention
    flash_attn<<<dim3(16, HQ_, BS_), 256, FA_BYTES>>>(pqh, pql, pkh, pkl, pvth, pvtl, paoh, paol);

    // output projection + final rmsnorm
    mm_bf16<<<dim3(16, 33), 128, MM_DSMEM>>>(paoh, paol, pwoh, pwol, po, HQ_*HD_, DIM_);
    final_rms<<<NTOK, 256>>>(po, anw, mod, out);
}

// round 7
// speedup vs baseline: 6.0331x; 1.0202x over previous
#include <cuda_runtime.h>
#include <cuda_bf16.h>
#include <math.h>
#include <cstdint>

// ---------------- problem constants ----------------
#define E_   2
#define HQ_  16
#define HK_  8
#define HD_  128
#define DIM_ 2048
#define BS_  2
#define SEQ_ 2048
#define NTOK (BS_*SEQ_)          // 4096
#define EPS_ 1e-6f
#define SCALE_ 0.08838834764831845f   // 1/sqrt(128)

typedef __nv_bfloat16 bf16;

// ---------------- scratch (device globals) ----------------
__device__ float g_v [NTOK * (HK_*HD_)];
__device__ float g_o [NTOK * DIM_];
__device__ int   g_perm[NTOK];
__device__ int   g_c0;

// bf16 split buffers
__device__ bf16 g_xh [NTOK*DIM_],      g_xl [NTOK*DIM_];
__device__ bf16 g_wqh[E_*DIM_*HQ_*HD_], g_wql[E_*DIM_*HQ_*HD_];
__device__ bf16 g_wkh[E_*DIM_*HK_*HD_], g_wkl[E_*DIM_*HK_*HD_];
__device__ bf16 g_wvh[E_*DIM_*HK_*HD_], g_wvl[E_*DIM_*HK_*HD_];
__device__ bf16 g_woh[E_*DIM_*HQ_*HD_], g_wol[E_*DIM_*HQ_*HD_];
__device__ bf16 g_qh [NTOK*(HQ_*HD_)],  g_ql [NTOK*(HQ_*HD_)];
__device__ bf16 g_kh [NTOK*(HK_*HD_)],  g_kl [NTOK*(HK_*HD_)];
__device__ bf16 g_vth[NTOK*(HK_*HD_)],  g_vtl[NTOK*(HK_*HD_)];   // [b][kvh][d][seq]
__device__ bf16 g_aoh[NTOK*(HQ_*HD_)],  g_aol[NTOK*(HQ_*HD_)];

// =============================== helpers ===============================
__device__ __forceinline__ uint32_t smem_u32(const void* p) {
    uint32_t a;
    asm("{ .reg .u64 t; cvta.to.shared.u64 t, %1; cvt.u32.u64 %0, t; }" : "=r"(a) : "l"(p));
    return a;
}
#define CP_ASYNC16(dst, src) \
    asm volatile("cp.async.cg.shared.global [%0], [%1], 16;" :: "r"(dst), "l"(src) : "memory")
#define CP_COMMIT() asm volatile("cp.async.commit_group;" ::: "memory")
template<int N> __device__ __forceinline__ void cp_wait() {
    asm volatile("cp.async.wait_group %0;" :: "n"(N) : "memory");
}

__device__ __forceinline__ void bsplit(float x, uint16_t& h, uint16_t& l) {
    bf16 bh = __float2bfloat16_rn(x);
    h = __bfloat16_as_ushort(bh);
    l = __bfloat16_as_ushort(__float2bfloat16_rn(x - __bfloat162float(bh)));
}
__device__ __forceinline__ uint32_t packb(uint16_t lo_elem, uint16_t hi_elem) {
    return (uint32_t)lo_elem | ((uint32_t)hi_elem << 16);
}
__device__ __forceinline__ void mma16816(float* c, const uint32_t* a, const uint32_t* b) {
    asm volatile("mma.sync.aligned.m16n8k16.row.col.f32.bf16.bf16.f32 "
        "{%0,%1,%2,%3}, {%4,%5,%6,%7}, {%8,%9}, {%0,%1,%2,%3};"
        : "+f"(c[0]), "+f"(c[1]), "+f"(c[2]), "+f"(c[3])
        : "r"(a[0]), "r"(a[1]), "r"(a[2]), "r"(a[3]), "r"(b[0]), "r"(b[1]));
}
__device__ __forceinline__ uint32_t sw256(int r, int off) {
    return (uint32_t)(r*256 + (off ^ ((r & 7) << 4)));
}
__device__ __forceinline__ uint32_t sw128(int r, int off) {
    return (uint32_t)(r*128 + (off ^ ((r & 7) << 4)));
}

// ============================================================================
// sort tokens by modality (stable counting sort), deterministic
// ============================================================================
__global__ __launch_bounds__(1024) void sort_tokens(const int* __restrict__ mod)
{
    __shared__ int s[1024];
    const int tid = threadIdx.x;
    int m[4]; int cnt = 0;
#pragma unroll
    for (int u = 0; u < 4; u++) { m[u] = mod[tid*4 + u]; cnt += (m[u] == 0); }
    s[tid] = cnt;
    __syncthreads();
    for (int off = 1; off < 1024; off <<= 1) {
        int v = (tid >= off) ? s[tid - off] : 0;
        __syncthreads();
        s[tid] += v;
        __syncthreads();
    }
    const int c0 = s[1023];
    if (tid == 0) g_c0 = c0;
    int r0 = s[tid] - cnt;
#pragma unroll
    for (int u = 0; u < 4; u++) {
        int g = tid*4 + u;
        if (m[u] == 0) { g_perm[r0] = g; r0++; }
        else           { g_perm[c0 + g - r0] = g; }
    }
}

// ============================================================================
// elementwise fp32 -> bf16 hi/lo split (for x)
// ============================================================================
__global__ __launch_bounds__(256) void split_f32(
    const float* __restrict__ in, bf16* __restrict__ hi, bf16* __restrict__ lo, int n4)
{
    int i = blockIdx.x * 256 + threadIdx.x;
    if (i >= n4) return;
    float4 v = ((const float4*)in)[i];
    uint16_t hx,lx,hy,ly,hz,lz,hw,lw;
    bsplit(v.x,hx,lx); bsplit(v.y,hy,ly); bsplit(v.z,hz,lz); bsplit(v.w,hw,lw);
    ((uint2*)hi)[i] = make_uint2(packb(hx,hy), packb(hz,hw));
    ((uint2*)lo)[i] = make_uint2(packb(lx,ly), packb(lz,lw));
}

// ============================================================================
// weight transpose-split: W [e][K][NC] fp32 -> T [e][NC][K] bf16 hi/lo
// ============================================================================
__global__ __launch_bounds__(256) void wtrans_split(
    const float* __restrict__ W, bf16* __restrict__ Th, bf16* __restrict__ Tl,
    int K, int NC)
{
    __shared__ float t[32][33];
    const int e  = blockIdx.z;
    const int k0 = blockIdx.x * 32, n0 = blockIdx.y * 32;
    const int tx = threadIdx.x & 31, ty = threadIdx.x >> 5;
    const float* Wp = W + (size_t)e * K * NC;
    for (int r = ty; r < 32; r += 8)
        t[r][tx] = Wp[(size_t)(k0 + r) * NC + n0 + tx];
    __syncthreads();
    bf16* th = Th + (size_t)e * NC * K;
    bf16* tl = Tl + (size_t)e * NC * K;
    for (int r = ty; r < 32; r += 8) {
        float v = t[tx][r];
        uint16_t h, l; bsplit(v, h, l);
        size_t o = (size_t)(n0 + r) * K + k0 + tx;
        th[o] = __ushort_as_bfloat16(h);
        tl[o] = __ushort_as_bfloat16(l);
    }
}

// ============================================================================
// V transpose-split: g_v fp32 [b*2048+s][kvh*128+d] -> Vt [b][kvh][d][seq] hi/lo
// ============================================================================
__global__ __launch_bounds__(256) void vtrans_split(
    const float* __restrict__ V, bf16* __restrict__ Th, bf16* __restrict__ Tl)
{
    __shared__ float t[32][33];
    const int s0 = blockIdx.x * 32, d0 = blockIdx.y * 32;
    const int z  = blockIdx.z;                 // b*8 + kvh
    const int b  = z >> 3, kvh = z & 7;
    const int tx = threadIdx.x & 31, ty = threadIdx.x >> 5;
    for (int r = ty; r < 32; r += 8)
        t[r][tx] = V[(size_t)(b*SEQ_ + s0 + r) * (HK_*HD_) + kvh*HD_ + d0 + tx];
    __syncthreads();
    for (int r = ty; r < 32; r += 8) {
        float v = t[tx][r];
        uint16_t h, l; bsplit(v, h, l);
        size_t o = (size_t)(z*HD_ + d0 + r) * SEQ_ + s0 + tx;
        Th[o] = __ushort_as_bfloat16(h);
        Tl[o] = __ushort_as_bfloat16(l);
    }
}

// ============================================================================
// bf16x2 mma.sync GEMM over expert-sorted rows.
// MODE 0: plain fp32 store (V, WO).
// MODE 1: fused per-head RMSNorm + RoPE epilogue, bf16 hi/lo store (Q, K).
//         Requires NC tile (128) == head span: true for Q (2048) and K (1024).
// Tile 128x128, BK=32, 128 threads (4 warps, 64x64 each), cp.async 2-stage.
// ============================================================================
#define MM_STAGE 40960          // Ah 10240 | Al | Bh | Bl
#define MM_DSMEM (2*MM_STAGE)

template<int MODE>
__global__ __launch_bounds__(128) void mm_bf16(
    const bf16* __restrict__ Ah, const bf16* __restrict__ Al,
    const bf16* __restrict__ Bh, const bf16* __restrict__ Bl,
    float* __restrict__ Cf,
    bf16* __restrict__ Ch, bf16* __restrict__ Cl,
    const float* __restrict__ normw,
    const float* __restrict__ fcos, const float* __restrict__ fsin,
    int K, int NC)
{
    extern __shared__ char sm[];
    __shared__ int sPerm[128];
    __shared__ float sred[4][64];
    const int tid  = threadIdx.x;
    const int lane = tid & 31;
    const int w    = tid >> 5;
    const int wm64 = (w & 1) * 64;
    const int wn64 = (w >> 1) * 64;
    const int bn   = blockIdx.x * 128;
    const int by   = blockIdx.y;

    const int c0 = g_c0;
    const int T0 = (c0 + 127) >> 7;
    const int T1 = (NTOK - c0 + 127) >> 7;
    if (by >= T0 + T1) return;
    const int e       = (by < T0) ? 0 : 1;
    const int rowbase = e ? (c0 + (by - T0) * 128) : (by * 128);
    const int limit   = e ? NTOK : c0;
    const size_t bofs = (size_t)e * NC * K + (size_t)bn * K;

    {
        int gs = rowbase + tid;
        sPerm[tid] = g_perm[gs < NTOK ? gs : (NTOK - 1)];
    }
    __syncthreads();

    const uint32_t sb = smem_u32(sm);

    auto load_chunk = [&](int cc, int p) {
        const int k0 = cc * 32;
        const uint32_t base = sb + p * MM_STAGE;
#pragma unroll
        for (int i = 0; i < 8; i++) {          // A: 1024 16B chunks (hi+lo)
            int idx = tid + (i << 7);
            int comp = idx >> 9, rem = idx & 511;
            int r = rem >> 2, c = rem & 3;
            const bf16* src = (comp ? Al : Ah) + (size_t)sPerm[r] * K + k0 + c * 8;
            CP_ASYNC16(base + comp*10240 + (uint32_t)(r*80 + c*16), src);
        }
#pragma unroll
        for (int i = 0; i < 8; i++) {          // B: 1024 16B chunks (hi+lo)
            int idx = tid + (i << 7);
            int comp = idx >> 9, rem = idx & 511;
            int r = rem >> 2, c = rem & 3;
            const bf16* src = (comp ? Bl : Bh) + bofs + (size_t)r * K + k0 + c * 8;
            CP_ASYNC16(base + 20480 + comp*10240 + (uint32_t)(r*80 + c*16), src);
        }
    };

    float acc[4][8][4];
#pragma unroll
    for (int i = 0; i < 4; i++)
#pragma unroll
        for (int j = 0; j < 8; j++)
#pragma unroll
            for (int q = 0; q < 4; q++) acc[i][j][q] = 0.f;

    const int NCH = K / 32;
    load_chunk(0, 0); CP_COMMIT();
    load_chunk(1, 1); CP_COMMIT();

    const int lr = lane >> 2;
    const int lc = lane & 3;

    for (int c = 0; c < NCH; c++) {
        cp_wait<1>();
        __syncthreads();
        const char* ah_s = sm + (c & 1) * MM_STAGE;
        const char* al_s = ah_s + 10240;
        const char* bh_s = ah_s + 20480;
        const char* bl_s = ah_s + 30720;
#pragma unroll
        for (int ks = 0; ks < 2; ks++) {
            const int b0 = ks * 32 + lc * 4;
            uint32_t fah[4][4], fal[4][4];
#pragma unroll
            for (int i = 0; i < 4; i++) {
                int m = wm64 + i * 16 + lr;
                fah[i][0] = *(const uint32_t*)(ah_s + m*80 + b0);
                fah[i][1] = *(const uint32_t*)(ah_s + (m+8)*80 + b0);
                fah[i][2] = *(const uint32_t*)(ah_s + m*80 + b0 + 16);
                fah[i][3] = *(const uint32_t*)(ah_s + (m+8)*80 + b0 + 16);
                fal[i][0] = *(const uint32_t*)(al_s + m*80 + b0);
                fal[i][1] = *(const uint32_t*)(al_s + (m+8)*80 + b0);
                fal[i][2] = *(const uint32_t*)(al_s + m*80 + b0 + 16);
                fal[i][3] = *(const uint32_t*)(al_s + (m+8)*80 + b0 + 16);
            }
#pragma unroll
            for (int j = 0; j < 8; j++) {
                int n = wn64 + j * 8 + lr;
                uint32_t fbh[2], fbl[2];
                fbh[0] = *(const uint32_t*)(bh_s + n*80 + b0);
                fbh[1] = *(const uint32_t*)(bh_s + n*80 + b0 + 16);
                fbl[0] = *(const uint32_t*)(bl_s + n*80 + b0);
                fbl[1] = *(const uint32_t*)(bl_s + n*80 + b0 + 16);
#pragma unroll
                for (int i = 0; i < 4; i++) {
                    mma16816(acc[i][j], fah[i], fbh);
                    mma16816(acc[i][j], fal[i], fbh);
                    mma16816(acc[i][j], fah[i], fbl);
                }
            }
        }
        __syncthreads();
        if (c + 2 < NCH) load_chunk(c + 2, c & 1);
        CP_COMMIT();
    }

    if (MODE == 0) {
        // plain fp32 scatter
#pragma unroll
        for (int i = 0; i < 4; i++) {
            int lr0 = wm64 + i * 16 + lr;
            bool v0 = (rowbase + lr0)     < limit;
            bool v1 = (rowbase + lr0 + 8) < limit;
            int t0 = v0 ? sPerm[lr0]     : 0;
            int t1 = v1 ? sPerm[lr0 + 8] : 0;
#pragma unroll
            for (int j = 0; j < 8; j++) {
                int cb = bn + wn64 + j * 8 + (lc << 1);
                if (v0) *(float2*)&Cf[(size_t)t0 * NC + cb] = make_float2(acc[i][j][0], acc[i][j][1]);
                if (v1) *(float2*)&Cf[(size_t)t1 * NC + cb] = make_float2(acc[i][j][2], acc[i][j][3]);
            }
        }
    } else {
        // fused per-head RMSNorm + RoPE + bf16 split store.
        // 1) row sums of squares over this warp's 64 cols
        float rs[4][2];
#pragma unroll
        for (int i = 0; i < 4; i++) {
            float s0 = 0.f, s1 = 0.f;
#pragma unroll
            for (int j = 0; j < 8; j++) {
                s0 += acc[i][j][0]*acc[i][j][0] + acc[i][j][1]*acc[i][j][1];
                s1 += acc[i][j][2]*acc[i][j][2] + acc[i][j][3]*acc[i][j][3];
            }
            rs[i][0] = s0; rs[i][1] = s1;
        }
#pragma unroll
        for (int i = 0; i < 4; i++) {
#pragma unroll
            for (int hh = 0; hh < 2; hh++) {
                rs[i][hh] += __shfl_xor_sync(0xffffffffu, rs[i][hh], 1);
                rs[i][hh] += __shfl_xor_sync(0xffffffffu, rs[i][hh], 2);
            }
        }
        if (lc == 0) {
#pragma unroll
            for (int i = 0; i < 4; i++) {
                sred[w][i*16 + lr]     = rs[i][0];
                sred[w][i*16 + 8 + lr] = rs[i][1];
            }
        }
        __syncthreads();
        float rinv[4][2];
#pragma unroll
        for (int i = 0; i < 4; i++) {
            float t0 = rs[i][0] + sred[w ^ 2][i*16 + lr];
            float t1 = rs[i][1] + sred[w ^ 2][i*16 + 8 + lr];
            rinv[i][0] = rsqrtf(t0 * (1.0f/HD_) + EPS_);
            rinv[i][1] = rsqrtf(t1 * (1.0f/HD_) + EPS_);
        }
        // 2) scale + weight + rope + split + store
#pragma unroll
        for (int i = 0; i < 4; i++) {
            const int lr0 = wm64 + i * 16 + lr;
            const bool v0 = (rowbase + lr0)     < limit;
            const bool v1 = (rowbase + lr0 + 8) < limit;
            const int t0 = sPerm[lr0], t1 = sPerm[lr0 + 8];
            const int s0 = t0 & (SEQ_-1), s1 = t1 & (SEQ_-1);
#pragma unroll
            for (int j = 0; j < 8; j++) {
                const int col0 = wn64 + j*8 + (lc << 1);      // even col in head
                const float2 nw = *(const float2*)&normw[e*HD_ + col0];
                const int cp = col0 >> 1;
                if (v0) {
                    float a0 = acc[i][j][0] * rinv[i][0] * nw.x;
                    float a1 = acc[i][j][1] * rinv[i][0] * nw.y;
                    float cc = fcos[s0*(HD_/2) + cp], sn = fsin[s0*(HD_/2) + cp];
                    float e0 = a0*cc - a1*sn, e1 = a0*sn + a1*cc;
                    uint16_t h0,l0,h1,l1;
                    bsplit(e0,h0,l0); bsplit(e1,h1,l1);
                    size_t off = (size_t)t0 * NC + bn + col0;
                    *(uint32_t*)((char*)Ch + 2*off) = packb(h0,h1);
                    *(uint32_t*)((char*)Cl + 2*off) = packb(l0,l1);
                }
                if (v1) {
                    float a0 = acc[i][j][2] * rinv[i][1] * nw.x;
                    float a1 = acc[i][j][3] * rinv[i][1] * nw.y;
                    float cc = fcos[s1*(HD_/2) + cp], sn = fsin[s1*(HD_/2) + cp];
                    float e0 = a0*cc - a1*sn, e1 = a0*sn + a1*cc;
                    uint16_t h0,l0,h1,l1;
                    bsplit(e0,h0,l0); bsplit(e1,h1,l1);
                    size_t off = (size_t)t1 * NC + bn + col0;
                    *(uint32_t*)((char*)Ch + 2*off) = packb(h0,h1);
                    *(uint32_t*)((char*)Cl + 2*off) = packb(l0,l1);
                }
            }
        }
    }
}

// ============================================================================
// Tensor-core causal flash attention (bf16x2), GQA kv = h>>1.
// CTA: 128 q-rows x one head, 256 threads (8 warps x 16 rows), kv tiles 64.
// P stays entirely in registers (S C-frag == PV A-frag layout).
// smem: Qh 32K | Ql 32K | K[2] (h16+l16) | Vt[2] (h16+l16)  = 192K
// ============================================================================
#define FQ_H 0
#define FQ_L 32768
#define FK(p) (65536  + (p)*32768)
#define FV(p) (131072 + (p)*32768)
#define FA_BYTES 196608

__global__ __launch_bounds__(256) void flash_attn(
    const bf16* __restrict__ Qh, const bf16* __restrict__ Ql,
    const bf16* __restrict__ Kh, const bf16* __restrict__ Kl,
    const bf16* __restrict__ Vth, const bf16* __restrict__ Vtl,
    bf16* __restrict__ AOh, bf16* __restrict__ AOl)
{
    extern __shared__ char sm[];
    const int tid  = threadIdx.x;
    const int lane = tid & 31;
    const int w    = tid >> 5;
    const int lr   = lane >> 2;
    const int lc   = lane & 3;

    const int qt = 15 - blockIdx.x;      // big tiles first
    const int h  = blockIdx.y;
    const int b  = blockIdx.z;
    const int kvh   = h >> 1;
    const int qbase = qt * 128;
    const int m0    = w * 16;
    const int niter = 2 * qt + 2;

    const uint32_t sb = smem_u32(sm);

    // ---- Q load (hi+lo) ----
#pragma unroll
    for (int i = 0; i < 16; i++) {
        int idx = tid + (i << 8);
        int comp = idx >> 11, rem = idx & 2047;
        int r = rem >> 4, c = rem & 15;
        const bf16* src = (comp ? Ql : Qh)
            + (size_t)(b*SEQ_ + qbase + r)*(HQ_*HD_) + h*HD_ + c*8;
        CP_ASYNC16(sb + (comp ? FQ_L : FQ_H) + sw256(r, c*16), src);
    }
    CP_COMMIT();

    auto load_k = [&](int kt, int p) {
#pragma unroll
        for (int i = 0; i < 8; i++) {
            int idx = tid + (i << 8);
            int comp = idx >> 10, rem = idx & 1023;
            int r = rem >> 4, c = rem & 15;
            const bf16* src = (comp ? Kl : Kh)
                + (size_t)(b*SEQ_ + kt*64 + r)*(HK_*HD_) + kvh*HD_ + c*8;
            CP_ASYNC16(sb + FK(p) + comp*16384 + sw256(r, c*16), src);
        }
        CP_COMMIT();
    };
    auto load_v = [&](int kt, int p) {
#pragma unroll
        for (int i = 0; i < 8; i++) {
            int idx = tid + (i << 8);
            int comp = idx >> 10, rem = idx & 1023;
            int r = rem >> 3, c = rem & 7;       // 128 d-rows x 8 chunks
            const bf16* src = (comp ? Vtl : Vth)
                + (size_t)((b*HK_ + kvh)*HD_ + r)*SEQ_ + kt*64 + c*8;
            CP_ASYNC16(sb + FV(p) + comp*16384 + sw128(r, c*16), src);
        }
        CP_COMMIT();
    };

    load_k(0, 0);
    load_v(0, 0);

    float o[16][4];
#pragma unroll
    for (int j = 0; j < 16; j++)
#pragma unroll
        for (int q = 0; q < 4; q++) o[j][q] = 0.f;
    float mr0 = -1e30f, mr1 = -1e30f, lr0s = 0.f, lr1s = 0.f;

    const int row0g = qbase + m0 + lr;

    for (int kt = 0; kt < niter; kt++) {
        const int p = kt & 1;
        cp_wait<1>();
        __syncthreads();
        if (kt + 1 < niter) { load_k(kt + 1, p ^ 1); load_v(kt + 1, p ^ 1); }

        const char* kh_s = sm + FK(p);
        const char* kl_s = kh_s + 16384;
        const char* qh_s = sm + FQ_H;
        const char* ql_s = sm + FQ_L;

        // ---- S = Q K^T (bf16x2) ----
        float sa[8][4];
#pragma unroll
        for (int j = 0; j < 8; j++)
#pragma unroll
            for (int q = 0; q < 4; q++) sa[j][q] = 0.f;
#pragma unroll
        for (int s = 0; s < 8; s++) {
            const int b0 = s*32 + lc*4;
            uint32_t fqh[4], fql[4];
            fqh[0] = *(const uint32_t*)(qh_s + sw256(m0 + lr,     b0));
            fqh[1] = *(const uint32_t*)(qh_s + sw256(m0 + 8 + lr, b0));
            fqh[2] = *(const uint32_t*)(qh_s + sw256(m0 + lr,     b0 + 16));
            fqh[3] = *(const uint32_t*)(qh_s + sw256(m0 + 8 + lr, b0 + 16));
            fql[0] = *(const uint32_t*)(ql_s + sw256(m0 + lr,     b0));
            fql[1] = *(const uint32_t*)(ql_s + sw256(m0 + 8 + lr, b0));
            fql[2] = *(const uint32_t*)(ql_s + sw256(m0 + lr,     b0 + 16));
            fql[3] = *(const uint32_t*)(ql_s + sw256(m0 + 8 + lr, b0 + 16));
#pragma unroll
            for (int j = 0; j < 8; j++) {
                const int n = j*8 + lr;
                uint32_t fkh[2], fkl[2];
                fkh[0] = *(const uint32_t*)(kh_s + sw256(n, b0));
                fkh[1] = *(const uint32_t*)(kh_s + sw256(n, b0 + 16));
                fkl[0] = *(const uint32_t*)(kl_s + sw256(n, b0));
                fkl[1] = *(const uint32_t*)(kl_s + sw256(n, b0 + 16));
                mma16816(sa[j], fqh, fkh);
                mma16816(sa[j], fql, fkh);
                mma16816(sa[j], fqh, fkl);
            }
        }

        // ---- online softmax ----
        const bool need_mask = (kt >= 2*qt);
        float mx0 = -1e30f, mx1 = -1e30f;
#pragma unroll
        for (int j = 0; j < 8; j++) {
            const int cb = kt*64 + j*8 + 2*lc;
#pragma unroll
            for (int q = 0; q < 4; q++) {
                float v = sa[j][q] * SCALE_;
                if (need_mask) {
                    int col = cb + (q & 1);
                    int row = (q < 2) ? row0g : (row0g + 8);
                    if (col > row) v = -1e30f;
                }
                sa[j][q] = v;
            }
            mx0 = fmaxf(mx0, fmaxf(sa[j][0], sa[j][1]));
            mx1 = fmaxf(mx1, fmaxf(sa[j][2], sa[j][3]));
        }
        mx0 = fmaxf(mx0, __shfl_xor_sync(0xffffffffu, mx0, 1));
        mx0 = fmaxf(mx0, __shfl_xor_sync(0xffffffffu, mx0, 2));
        mx1 = fmaxf(mx1, __shfl_xor_sync(0xffffffffu, mx1, 1));
        mx1 = fmaxf(mx1, __shfl_xor_sync(0xffffffffu, mx1, 2));
        const float mn0 = fmaxf(mr0, mx0);
        const float mn1 = fmaxf(mr1, mx1);
        const float c0 = __expf(mr0 - mn0);
        const float c1 = __expf(mr1 - mn1);
        float ps0 = 0.f, ps1 = 0.f;
#pragma unroll
        for (int j = 0; j < 8; j++) {
            sa[j][0] = __expf(sa[j][0] - mn0);
            sa[j][1] = __expf(sa[j][1] - mn0);
            sa[j][2] = __expf(sa[j][2] - mn1);
            sa[j][3] = __expf(sa[j][3] - mn1);
            ps0 += sa[j][0] + sa[j][1];
            ps1 += sa[j][2] + sa[j][3];
        }
        ps0 += __shfl_xor_sync(0xffffffffu, ps0, 1);
        ps0 += __shfl_xor_sync(0xffffffffu, ps0, 2);
        ps1 += __shfl_xor_sync(0xffffffffu, ps1, 1);
        ps1 += __shfl_xor_sync(0xffffffffu, ps1, 2);
        lr0s = lr0s * c0 + ps0;
        lr1s = lr1s * c1 + ps1;
        mr0 = mn0; mr1 = mn1;
#pragma unroll
        for (int j = 0; j < 16; j++) {
            o[j][0] *= c0; o[j][1] *= c0;
            o[j][2] *= c1; o[j][3] *= c1;
        }

        // ---- P frags directly from registers (S C-frag == PV A-frag) ----
        uint32_t aph[4][4], apl[4][4];
#pragma unroll
        for (int t = 0; t < 4; t++) {
            uint16_t h0,l0,h1,l1;
            bsplit(sa[2*t][0],h0,l0);   bsplit(sa[2*t][1],h1,l1);
            aph[t][0] = packb(h0,h1);   apl[t][0] = packb(l0,l1);
            bsplit(sa[2*t][2],h0,l0);   bsplit(sa[2*t][3],h1,l1);
            aph[t][1] = packb(h0,h1);   apl[t][1] = packb(l0,l1);
            bsplit(sa[2*t+1][0],h0,l0); bsplit(sa[2*t+1][1],h1,l1);
            aph[t][2] = packb(h0,h1);   apl[t][2] = packb(l0,l1);
            bsplit(sa[2*t+1][2],h0,l0); bsplit(sa[2*t+1][3],h1,l1);
            aph[t][3] = packb(h0,h1);   apl[t][3] = packb(l0,l1);
        }

        // ---- V ready ----
        if (kt + 1 < niter) cp_wait<2>(); else cp_wait<0>();
        __syncthreads();
        const char* vh_s = sm + FV(p);
        const char* vl_s = vh_s + 16384;

        // ---- O += P V (bf16x2) ----
#pragma unroll
        for (int t = 0; t < 4; t++) {
            const int b0 = t*32 + lc*4;
#pragma unroll
            for (int j = 0; j < 16; j++) {
                const int n = j*8 + lr;
                uint32_t fvh[2], fvl[2];
                fvh[0] = *(const uint32_t*)(vh_s + sw128(n, b0));
                fvh[1] = *(const uint32_t*)(vh_s + sw128(n, b0 + 16));
                fvl[0] = *(const uint32_t*)(vl_s + sw128(n, b0));
                fvl[1] = *(const uint32_t*)(vl_s + sw128(n, b0 + 16));
                mma16816(o[j], aph[t], fvh);
                mma16816(o[j], apl[t], fvh);
                mma16816(o[j], aph[t], fvl);
            }
        }
    }

    // ---- normalize + split-store AO ----
    const float i0 = 1.f / lr0s;
    const float i1 = 1.f / lr1s;
    const size_t t0 = (size_t)(b*SEQ_ + row0g);
    const size_t t1 = t0 + 8;
#pragma unroll
    for (int j = 0; j < 16; j++) {
        const int col = h*HD_ + j*8 + 2*lc;
        uint16_t h0,l0,h1,l1;
        bsplit(o[j][0]*i0, h0, l0); bsplit(o[j][1]*i0, h1, l1);
        size_t off0 = t0*(HQ_*HD_) + col;
        *(uint32_t*)((char*)AOh + 2*off0) = packb(h0, h1);
        *(uint32_t*)((char*)AOl + 2*off0) = packb(l0, l1);
        bsplit(o[j][2]*i1, h0, l0); bsplit(o[j][3]*i1, h1, l1);
        size_t off1 = t1*(HQ_*HD_) + col;
        *(uint32_t*)((char*)AOh + 2*off1) = packb(h0, h1);
        *(uint32_t*)((char*)AOl + 2*off1) = packb(l0, l1);
    }
}

// ============================================================================
// Final per-token RMSNorm over DIM with attn_norm_w[expert]
// ============================================================================
__global__ __launch_bounds__(256) void final_rms(
    const float* __restrict__ in, const float* __restrict__ w,
    const int* __restrict__ mod, float* __restrict__ out)
{
    const int n = blockIdx.x;
    const int tid = threadIdx.x;
    const int e = mod[n];
    const float* row = in + (size_t)n*DIM_;
    float vals[8];
    float ss = 0.f;
#pragma unroll
    for (int u = 0; u < 8; u++) {
        float v = row[tid + u*256];
        vals[u] = v;
        ss += v*v;
    }
#pragma unroll
    for (int o = 16; o > 0; o >>= 1) ss += __shfl_xor_sync(0xffffffffu, ss, o);
    __shared__ float wsum[8];
    if ((tid & 31) == 0) wsum[tid >> 5] = ss;
    __syncthreads();
    float tot = 0.f;
#pragma unroll
    for (int i = 0; i < 8; i++) tot += wsum[i];
    float r = rsqrtf(tot * (1.0f/DIM_) + EPS_);
#pragma unroll
    for (int u = 0; u < 8; u++)
        out[(size_t)n*DIM_ + tid + u*256] = vals[u] * r * w[e*DIM_ + tid + u*256];
}

// ============================================================================
// launch
// ============================================================================
extern "C" void kernel_launch(void* const* d_in, const int* in_sizes, int n_in,
                              void* d_out, int out_size)
{
    const float* x    = (const float*)d_in[0];
    const float* fcos = (const float*)d_in[1];
    const float* fsin = (const float*)d_in[2];
    const float* wq   = (const float*)d_in[3];
    const float* wk   = (const float*)d_in[4];
    const float* wv   = (const float*)d_in[5];
    const float* wo   = (const float*)d_in[6];
    const float* qnw  = (const float*)d_in[7];
    const float* knw  = (const float*)d_in[8];
    const float* anw  = (const float*)d_in[9];
    const int*   mod  = (const int*)d_in[10];
    float* out = (float*)d_out;

    float *pv, *po;
    bf16 *pxh, *pxl, *pwqh, *pwql, *pwkh, *pwkl, *pwvh, *pwvl, *pwoh, *pwol;
    bf16 *pqh, *pql, *pkh, *pkl, *pvth, *pvtl, *paoh, *paol;
    cudaGetSymbolAddress((void**)&pv,  g_v);
    cudaGetSymbolAddress((void**)&po,  g_o);
    cudaGetSymbolAddress((void**)&pxh, g_xh);  cudaGetSymbolAddress((void**)&pxl, g_xl);
    cudaGetSymbolAddress((void**)&pwqh, g_wqh); cudaGetSymbolAddress((void**)&pwql, g_wql);
    cudaGetSymbolAddress((void**)&pwkh, g_wkh); cudaGetSymbolAddress((void**)&pwkl, g_wkl);
    cudaGetSymbolAddress((void**)&pwvh, g_wvh); cudaGetSymbolAddress((void**)&pwvl, g_wvl);
    cudaGetSymbolAddress((void**)&pwoh, g_woh); cudaGetSymbolAddress((void**)&pwol, g_wol);
    cudaGetSymbolAddress((void**)&pqh, g_qh);   cudaGetSymbolAddress((void**)&pql, g_ql);
    cudaGetSymbolAddress((void**)&pkh, g_kh);   cudaGetSymbolAddress((void**)&pkl, g_kl);
    cudaGetSymbolAddress((void**)&pvth, g_vth); cudaGetSymbolAddress((void**)&pvtl, g_vtl);
    cudaGetSymbolAddress((void**)&paoh, g_aoh); cudaGetSymbolAddress((void**)&paol, g_aol);

    cudaFuncSetAttribute(flash_attn, cudaFuncAttributeMaxDynamicSharedMemorySize, FA_BYTES);
    cudaFuncSetAttribute(mm_bf16<0>, cudaFuncAttributeMaxDynamicSharedMemorySize, MM_DSMEM);
    cudaFuncSetAttribute(mm_bf16<1>, cudaFuncAttributeMaxDynamicSharedMemorySize, MM_DSMEM);

    // preprocessing
    sort_tokens<<<1, 1024>>>(mod);
    split_f32<<<(NTOK*DIM_/4 + 255)/256, 256>>>(x, pxh, pxl, NTOK*DIM_/4);
    wtrans_split<<<dim3(64, 64, 2), 256>>>(wq, pwqh, pwql, DIM_, HQ_*HD_);
    wtrans_split<<<dim3(64, 32, 2), 256>>>(wk, pwkh, pwkl, DIM_, HK_*HD_);
    wtrans_split<<<dim3(64, 32, 2), 256>>>(wv, pwvh, pwvl, DIM_, HK_*HD_);
    wtrans_split<<<dim3(64, 64, 2), 256>>>(wo, pwoh, pwol, HQ_*HD_, DIM_);

    // Q/K projections with fused rmsnorm+rope -> bf16 split outputs
    mm_bf16<1><<<dim3(16, 33), 128, MM_DSMEM>>>(pxh, pxl, pwqh, pwql,
        nullptr, pqh, pql, qnw, fcos, fsin, DIM_, HQ_*HD_);
    mm_bf16<1><<<dim3( 8, 33), 128, MM_DSMEM>>>(pxh, pxl, pwkh, pwkl,
        nullptr, pkh, pkl, knw, fcos, fsin, DIM_, HK_*HD_);
    // V projection (fp32) + transpose-split
    mm_bf16<0><<<dim3( 8, 33), 128, MM_DSMEM>>>(pxh, pxl, pwvh, pwvl,
        pv, nullptr, nullptr, nullptr, nullptr, nullptr, DIM_, HK_*HD_);
    vtrans_split<<<dim3(64, 4, 16), 256>>>(pv, pvth, pvtl);

    // attention (P register-resident)
    flash_attn<<<dim3(16, HQ_, BS_), 256, FA_BYTES>>>(pqh, pql, pkh, pkl, pvth, pvtl, paoh, paol);

    // output projection + final rmsnorm
    mm_bf16<0><<<dim3(16, 33), 128, MM_DSMEM>>>(paoh, paol, pwoh, pwol,
        po, nullptr, nullptr, nullptr, nullptr, nullptr, HQ_*HD_, DIM_);
    final_rms<<<NTOK, 256>>>(po, anw, mod, out);
}

// round 8
// speedup vs baseline: 6.4979x; 1.0770x over previous
#include <cuda_runtime.h>
#include <cuda_bf16.h>
#include <math.h>
#include <cstdint>

// ---------------- problem constants ----------------
#define E_   2
#define HQ_  16
#define HK_  8
#define HD_  128
#define DIM_ 2048
#define BS_  2
#define SEQ_ 2048
#define NTOK (BS_*SEQ_)          // 4096
#define EPS_ 1e-6f
#define SCALE_ 0.08838834764831845f   // 1/sqrt(128)

typedef __nv_bfloat16 bf16;

// ---------------- scratch (device globals) ----------------
__device__ float g_v [NTOK * (HK_*HD_)];
__device__ float g_o [NTOK * DIM_];
__device__ int   g_perm[NTOK];
__device__ int   g_c0;

// bf16 split buffers
__device__ bf16 g_xh [NTOK*DIM_],      g_xl [NTOK*DIM_];
__device__ bf16 g_wqh[E_*DIM_*HQ_*HD_], g_wql[E_*DIM_*HQ_*HD_];
__device__ bf16 g_wkh[E_*DIM_*HK_*HD_], g_wkl[E_*DIM_*HK_*HD_];
__device__ bf16 g_wvh[E_*DIM_*HK_*HD_], g_wvl[E_*DIM_*HK_*HD_];
__device__ bf16 g_woh[E_*DIM_*HQ_*HD_], g_wol[E_*DIM_*HQ_*HD_];
__device__ bf16 g_qh [NTOK*(HQ_*HD_)],  g_ql [NTOK*(HQ_*HD_)];
__device__ bf16 g_kh [NTOK*(HK_*HD_)],  g_kl [NTOK*(HK_*HD_)];
__device__ bf16 g_vth[NTOK*(HK_*HD_)],  g_vtl[NTOK*(HK_*HD_)];   // [b][kvh][d][seq]
__device__ bf16 g_aoh[NTOK*(HQ_*HD_)],  g_aol[NTOK*(HQ_*HD_)];

// =============================== helpers ===============================
__device__ __forceinline__ uint32_t smem_u32(const void* p) {
    uint32_t a;
    asm("{ .reg .u64 t; cvta.to.shared.u64 t, %1; cvt.u32.u64 %0, t; }" : "=r"(a) : "l"(p));
    return a;
}
#define CP_ASYNC16(dst, src) \
    asm volatile("cp.async.cg.shared.global [%0], [%1], 16;" :: "r"(dst), "l"(src) : "memory")
#define CP_COMMIT() asm volatile("cp.async.commit_group;" ::: "memory")
template<int N> __device__ __forceinline__ void cp_wait() {
    asm volatile("cp.async.wait_group %0;" :: "n"(N) : "memory");
}
#define LDSM4(r0,r1,r2,r3, addr) \
    asm volatile("ldmatrix.sync.aligned.m8n8.x4.shared.b16 {%0,%1,%2,%3}, [%4];" \
        : "=r"(r0), "=r"(r1), "=r"(r2), "=r"(r3) : "r"(addr))

__device__ __forceinline__ void bsplit(float x, uint16_t& h, uint16_t& l) {
    bf16 bh = __float2bfloat16_rn(x);
    h = __bfloat16_as_ushort(bh);
    l = __bfloat16_as_ushort(__float2bfloat16_rn(x - __bfloat162float(bh)));
}
__device__ __forceinline__ uint32_t packb(uint16_t lo_elem, uint16_t hi_elem) {
    return (uint32_t)lo_elem | ((uint32_t)hi_elem << 16);
}
__device__ __forceinline__ void mma16816(float* c, const uint32_t* a, const uint32_t* b) {
    asm volatile("mma.sync.aligned.m16n8k16.row.col.f32.bf16.bf16.f32 "
        "{%0,%1,%2,%3}, {%4,%5,%6,%7}, {%8,%9}, {%0,%1,%2,%3};"
        : "+f"(c[0]), "+f"(c[1]), "+f"(c[2]), "+f"(c[3])
        : "r"(a[0]), "r"(a[1]), "r"(a[2]), "r"(a[3]), "r"(b[0]), "r"(b[1]));
}
__device__ __forceinline__ uint32_t sw256(int r, int off) {
    return (uint32_t)(r*256 + (off ^ ((r & 7) << 4)));
}
__device__ __forceinline__ uint32_t sw128(int r, int off) {
    return (uint32_t)(r*128 + (off ^ ((r & 7) << 4)));
}

// ============================================================================
// sort tokens by modality (stable counting sort), deterministic
// ============================================================================
__global__ __launch_bounds__(1024) void sort_tokens(const int* __restrict__ mod)
{
    __shared__ int s[1024];
    const int tid = threadIdx.x;
    int m[4]; int cnt = 0;
#pragma unroll
    for (int u = 0; u < 4; u++) { m[u] = mod[tid*4 + u]; cnt += (m[u] == 0); }
    s[tid] = cnt;
    __syncthreads();
    for (int off = 1; off < 1024; off <<= 1) {
        int v = (tid >= off) ? s[tid - off] : 0;
        __syncthreads();
        s[tid] += v;
        __syncthreads();
    }
    const int c0 = s[1023];
    if (tid == 0) g_c0 = c0;
    int r0 = s[tid] - cnt;
#pragma unroll
    for (int u = 0; u < 4; u++) {
        int g = tid*4 + u;
        if (m[u] == 0) { g_perm[r0] = g; r0++; }
        else           { g_perm[c0 + g - r0] = g; }
    }
}

// ============================================================================
// elementwise fp32 -> bf16 hi/lo split (for x)
// ============================================================================
__global__ __launch_bounds__(256) void split_f32(
    const float* __restrict__ in, bf16* __restrict__ hi, bf16* __restrict__ lo, int n4)
{
    int i = blockIdx.x * 256 + threadIdx.x;
    if (i >= n4) return;
    float4 v = ((const float4*)in)[i];
    uint16_t hx,lx,hy,ly,hz,lz,hw,lw;
    bsplit(v.x,hx,lx); bsplit(v.y,hy,ly); bsplit(v.z,hz,lz); bsplit(v.w,hw,lw);
    ((uint2*)hi)[i] = make_uint2(packb(hx,hy), packb(hz,hw));
    ((uint2*)lo)[i] = make_uint2(packb(lx,ly), packb(lz,lw));
}

// ============================================================================
// weight transpose-split: W [e][K][NC] fp32 -> T [e][NC][K] bf16 hi/lo
// ============================================================================
__global__ __launch_bounds__(256) void wtrans_split(
    const float* __restrict__ W, bf16* __restrict__ Th, bf16* __restrict__ Tl,
    int K, int NC)
{
    __shared__ float t[32][33];
    const int e  = blockIdx.z;
    const int k0 = blockIdx.x * 32, n0 = blockIdx.y * 32;
    const int tx = threadIdx.x & 31, ty = threadIdx.x >> 5;
    const float* Wp = W + (size_t)e * K * NC;
    for (int r = ty; r < 32; r += 8)
        t[r][tx] = Wp[(size_t)(k0 + r) * NC + n0 + tx];
    __syncthreads();
    bf16* th = Th + (size_t)e * NC * K;
    bf16* tl = Tl + (size_t)e * NC * K;
    for (int r = ty; r < 32; r += 8) {
        float v = t[tx][r];
        uint16_t h, l; bsplit(v, h, l);
        size_t o = (size_t)(n0 + r) * K + k0 + tx;
        th[o] = __ushort_as_bfloat16(h);
        tl[o] = __ushort_as_bfloat16(l);
    }
}

// ============================================================================
// V transpose-split: g_v fp32 [b*2048+s][kvh*128+d] -> Vt [b][kvh][d][seq] hi/lo
// ============================================================================
__global__ __launch_bounds__(256) void vtrans_split(
    const float* __restrict__ V, bf16* __restrict__ Th, bf16* __restrict__ Tl)
{
    __shared__ float t[32][33];
    const int s0 = blockIdx.x * 32, d0 = blockIdx.y * 32;
    const int z  = blockIdx.z;                 // b*8 + kvh
    const int b  = z >> 3, kvh = z & 7;
    const int tx = threadIdx.x & 31, ty = threadIdx.x >> 5;
    for (int r = ty; r < 32; r += 8)
        t[r][tx] = V[(size_t)(b*SEQ_ + s0 + r) * (HK_*HD_) + kvh*HD_ + d0 + tx];
    __syncthreads();
    for (int r = ty; r < 32; r += 8) {
        float v = t[tx][r];
        uint16_t h, l; bsplit(v, h, l);
        size_t o = (size_t)(z*HD_ + d0 + r) * SEQ_ + s0 + tx;
        Th[o] = __ushort_as_bfloat16(h);
        Tl[o] = __ushort_as_bfloat16(l);
    }
}

// ============================================================================
// bf16x2 mma.sync GEMM over expert-sorted rows, ldmatrix fragment loads.
// MODE 0: plain fp32 store (V, WO).
// MODE 1: fused per-head RMSNorm + RoPE epilogue, bf16 hi/lo store (Q, K).
// Tile 128x128, BK=32, 128 threads (4 warps, 64x64 each), cp.async 2-stage.
// smem rows padded to 80B -> conflict-free ldmatrix (8 rows distinct chunks).
// ============================================================================
#define MM_STAGE 40960          // Ah 10240 | Al | Bh | Bl
#define MM_DSMEM (2*MM_STAGE)

template<int MODE>
__global__ __launch_bounds__(128) void mm_bf16(
    const bf16* __restrict__ Ah, const bf16* __restrict__ Al,
    const bf16* __restrict__ Bh, const bf16* __restrict__ Bl,
    float* __restrict__ Cf,
    bf16* __restrict__ Ch, bf16* __restrict__ Cl,
    const float* __restrict__ normw,
    const float* __restrict__ fcos, const float* __restrict__ fsin,
    int K, int NC)
{
    extern __shared__ char sm[];
    __shared__ int sPerm[128];
    __shared__ float sred[4][64];
    const int tid  = threadIdx.x;
    const int lane = tid & 31;
    const int w    = tid >> 5;
    const int wm64 = (w & 1) * 64;
    const int wn64 = (w >> 1) * 64;
    const int bn   = blockIdx.x * 128;
    const int by   = blockIdx.y;

    const int c0 = g_c0;
    const int T0 = (c0 + 127) >> 7;
    const int T1 = (NTOK - c0 + 127) >> 7;
    if (by >= T0 + T1) return;
    const int e       = (by < T0) ? 0 : 1;
    const int rowbase = e ? (c0 + (by - T0) * 128) : (by * 128);
    const int limit   = e ? NTOK : c0;
    const size_t bofs = (size_t)e * NC * K + (size_t)bn * K;

    {
        int gs = rowbase + tid;
        sPerm[tid] = g_perm[gs < NTOK ? gs : (NTOK - 1)];
    }
    __syncthreads();

    const uint32_t sb = smem_u32(sm);

    auto load_chunk = [&](int cc, int p) {
        const int k0 = cc * 32;
        const uint32_t base = sb + p * MM_STAGE;
#pragma unroll
        for (int i = 0; i < 8; i++) {          // A: 1024 16B chunks (hi+lo)
            int idx = tid + (i << 7);
            int comp = idx >> 9, rem = idx & 511;
            int r = rem >> 2, c = rem & 3;
            const bf16* src = (comp ? Al : Ah) + (size_t)sPerm[r] * K + k0 + c * 8;
            CP_ASYNC16(base + comp*10240 + (uint32_t)(r*80 + c*16), src);
        }
#pragma unroll
        for (int i = 0; i < 8; i++) {          // B: 1024 16B chunks (hi+lo)
            int idx = tid + (i << 7);
            int comp = idx >> 9, rem = idx & 511;
            int r = rem >> 2, c = rem & 3;
            const bf16* src = (comp ? Bl : Bh) + bofs + (size_t)r * K + k0 + c * 8;
            CP_ASYNC16(base + 20480 + comp*10240 + (uint32_t)(r*80 + c*16), src);
        }
    };

    float acc[4][8][4];
#pragma unroll
    for (int i = 0; i < 4; i++)
#pragma unroll
        for (int j = 0; j < 8; j++)
#pragma unroll
            for (int q = 0; q < 4; q++) acc[i][j][q] = 0.f;

    const int NCH = K / 32;
    load_chunk(0, 0); CP_COMMIT();
    load_chunk(1, 1); CP_COMMIT();

    const int lr = lane >> 2;
    const int lc = lane & 3;
    // ldmatrix address decomposition
    const int g8  = lane & 7;
    const int grp = lane >> 3;                    // 0..3
    const int a_row = wm64 + (grp & 1) * 8 + g8;  // +i*16
    const int a_ofx = (grp >> 1) * 16;
    const int b_row = wn64 + (grp >> 1) * 8 + g8; // +jj*16
    const int b_ofx = (grp & 1) * 16;

    for (int c = 0; c < NCH; c++) {
        cp_wait<1>();
        __syncthreads();
        const uint32_t bb = sb + (c & 1) * MM_STAGE;
#pragma unroll
        for (int ks = 0; ks < 2; ks++) {
            const uint32_t koff = (uint32_t)(ks * 32);
            uint32_t fah[4][4], fal[4][4];
#pragma unroll
            for (int i = 0; i < 4; i++) {
                uint32_t aaddr = bb + (uint32_t)((a_row + i*16) * 80) + koff + a_ofx;
                LDSM4(fah[i][0], fah[i][1], fah[i][2], fah[i][3], aaddr);
                LDSM4(fal[i][0], fal[i][1], fal[i][2], fal[i][3], aaddr + 10240);
            }
            uint32_t fbh4[4][4], fbl4[4][4];
#pragma unroll
            for (int jj = 0; jj < 4; jj++) {
                uint32_t baddr = bb + 20480 + (uint32_t)((b_row + jj*16) * 80) + koff + b_ofx;
                LDSM4(fbh4[jj][0], fbh4[jj][1], fbh4[jj][2], fbh4[jj][3], baddr);
                LDSM4(fbl4[jj][0], fbl4[jj][1], fbl4[jj][2], fbl4[jj][3], baddr + 10240);
            }
#pragma unroll
            for (int jj = 0; jj < 4; jj++) {
#pragma unroll
                for (int half = 0; half < 2; half++) {
                    const int j = jj*2 + half;
                    uint32_t fbh[2] = { fbh4[jj][half*2], fbh4[jj][half*2+1] };
                    uint32_t fbl[2] = { fbl4[jj][half*2], fbl4[jj][half*2+1] };
#pragma unroll
                    for (int i = 0; i < 4; i++) {
                        mma16816(acc[i][j], fah[i], fbh);
                        mma16816(acc[i][j], fal[i], fbh);
                        mma16816(acc[i][j], fah[i], fbl);
                    }
                }
            }
        }
        __syncthreads();
        if (c + 2 < NCH) load_chunk(c + 2, c & 1);
        CP_COMMIT();
    }

    if (MODE == 0) {
        // plain fp32 scatter
#pragma unroll
        for (int i = 0; i < 4; i++) {
            int lr0 = wm64 + i * 16 + lr;
            bool v0 = (rowbase + lr0)     < limit;
            bool v1 = (rowbase + lr0 + 8) < limit;
            int t0 = v0 ? sPerm[lr0]     : 0;
            int t1 = v1 ? sPerm[lr0 + 8] : 0;
#pragma unroll
            for (int j = 0; j < 8; j++) {
                int cb = bn + wn64 + j * 8 + (lc << 1);
                if (v0) *(float2*)&Cf[(size_t)t0 * NC + cb] = make_float2(acc[i][j][0], acc[i][j][1]);
                if (v1) *(float2*)&Cf[(size_t)t1 * NC + cb] = make_float2(acc[i][j][2], acc[i][j][3]);
            }
        }
    } else {
        // fused per-head RMSNorm + RoPE + bf16 split store
        float rs[4][2];
#pragma unroll
        for (int i = 0; i < 4; i++) {
            float s0 = 0.f, s1 = 0.f;
#pragma unroll
            for (int j = 0; j < 8; j++) {
                s0 += acc[i][j][0]*acc[i][j][0] + acc[i][j][1]*acc[i][j][1];
                s1 += acc[i][j][2]*acc[i][j][2] + acc[i][j][3]*acc[i][j][3];
            }
            rs[i][0] = s0; rs[i][1] = s1;
        }
#pragma unroll
        for (int i = 0; i < 4; i++) {
#pragma unroll
            for (int hh = 0; hh < 2; hh++) {
                rs[i][hh] += __shfl_xor_sync(0xffffffffu, rs[i][hh], 1);
                rs[i][hh] += __shfl_xor_sync(0xffffffffu, rs[i][hh], 2);
            }
        }
        if (lc == 0) {
#pragma unroll
            for (int i = 0; i < 4; i++) {
                sred[w][i*16 + lr]     = rs[i][0];
                sred[w][i*16 + 8 + lr] = rs[i][1];
            }
        }
        __syncthreads();
        float rinv[4][2];
#pragma unroll
        for (int i = 0; i < 4; i++) {
            float t0 = rs[i][0] + sred[w ^ 2][i*16 + lr];
            float t1 = rs[i][1] + sred[w ^ 2][i*16 + 8 + lr];
            rinv[i][0] = rsqrtf(t0 * (1.0f/HD_) + EPS_);
            rinv[i][1] = rsqrtf(t1 * (1.0f/HD_) + EPS_);
        }
#pragma unroll
        for (int i = 0; i < 4; i++) {
            const int lr0 = wm64 + i * 16 + lr;
            const bool v0 = (rowbase + lr0)     < limit;
            const bool v1 = (rowbase + lr0 + 8) < limit;
            const int t0 = sPerm[lr0], t1 = sPerm[lr0 + 8];
            const int s0 = t0 & (SEQ_-1), s1 = t1 & (SEQ_-1);
#pragma unroll
            for (int j = 0; j < 8; j++) {
                const int col0 = wn64 + j*8 + (lc << 1);
                const float2 nw = *(const float2*)&normw[e*HD_ + col0];
                const int cp = col0 >> 1;
                if (v0) {
                    float a0 = acc[i][j][0] * rinv[i][0] * nw.x;
                    float a1 = acc[i][j][1] * rinv[i][0] * nw.y;
                    float cc = fcos[s0*(HD_/2) + cp], sn = fsin[s0*(HD_/2) + cp];
                    float e0 = a0*cc - a1*sn, e1 = a0*sn + a1*cc;
                    uint16_t h0,l0,h1,l1;
                    bsplit(e0,h0,l0); bsplit(e1,h1,l1);
                    size_t off = (size_t)t0 * NC + bn + col0;
                    *(uint32_t*)((char*)Ch + 2*off) = packb(h0,h1);
                    *(uint32_t*)((char*)Cl + 2*off) = packb(l0,l1);
                }
                if (v1) {
                    float a0 = acc[i][j][2] * rinv[i][1] * nw.x;
                    float a1 = acc[i][j][3] * rinv[i][1] * nw.y;
                    float cc = fcos[s1*(HD_/2) + cp], sn = fsin[s1*(HD_/2) + cp];
                    float e0 = a0*cc - a1*sn, e1 = a0*sn + a1*cc;
                    uint16_t h0,l0,h1,l1;
                    bsplit(e0,h0,l0); bsplit(e1,h1,l1);
                    size_t off = (size_t)t1 * NC + bn + col0;
                    *(uint32_t*)((char*)Ch + 2*off) = packb(h0,h1);
                    *(uint32_t*)((char*)Cl + 2*off) = packb(l0,l1);
                }
            }
        }
    }
}

// ============================================================================
// Tensor-core causal flash attention (bf16x2), ldmatrix frag loads.
// CTA: 128 q-rows x one head, 256 threads (8 warps x 16 rows), kv tiles 64.
// P register-resident. smem: Qh|Ql 64K, K[2] 64K, Vt[2] 64K = 192K.
// ============================================================================
#define FQ_H 0
#define FQ_L 32768
#define FK(p) (65536  + (p)*32768)
#define FV(p) (131072 + (p)*32768)
#define FA_BYTES 196608

__global__ __launch_bounds__(256) void flash_attn(
    const bf16* __restrict__ Qh, const bf16* __restrict__ Ql,
    const bf16* __restrict__ Kh, const bf16* __restrict__ Kl,
    const bf16* __restrict__ Vth, const bf16* __restrict__ Vtl,
    bf16* __restrict__ AOh, bf16* __restrict__ AOl)
{
    extern __shared__ char sm[];
    const int tid  = threadIdx.x;
    const int lane = tid & 31;
    const int w    = tid >> 5;
    const int lr   = lane >> 2;
    const int lc   = lane & 3;
    const int g8   = lane & 7;
    const int grp  = lane >> 3;

    const int qt = 15 - blockIdx.x;      // big tiles first
    const int h  = blockIdx.y;
    const int b  = blockIdx.z;
    const int kvh   = h >> 1;
    const int qbase = qt * 128;
    const int m0    = w * 16;
    const int niter = 2 * qt + 2;

    const uint32_t sb = smem_u32(sm);

    // ldmatrix address components
    const int q_row = m0 + (grp & 1) * 8 + g8;   // A-frag rows
    const int q_ofx = (grp >> 1) * 16;
    const int kv_row = (grp >> 1) * 8 + g8;      // B-frag rows (+tile*16)
    const int kv_ofx = (grp & 1) * 16;

    // ---- Q load (hi+lo) ----
#pragma unroll
    for (int i = 0; i < 16; i++) {
        int idx = tid + (i << 8);
        int comp = idx >> 11, rem = idx & 2047;
        int r = rem >> 4, c = rem & 15;
        const bf16* src = (comp ? Ql : Qh)
            + (size_t)(b*SEQ_ + qbase + r)*(HQ_*HD_) + h*HD_ + c*8;
        CP_ASYNC16(sb + (comp ? FQ_L : FQ_H) + sw256(r, c*16), src);
    }
    CP_COMMIT();

    auto load_k = [&](int kt, int p) {
#pragma unroll
        for (int i = 0; i < 8; i++) {
            int idx = tid + (i << 8);
            int comp = idx >> 10, rem = idx & 1023;
            int r = rem >> 4, c = rem & 15;
            const bf16* src = (comp ? Kl : Kh)
                + (size_t)(b*SEQ_ + kt*64 + r)*(HK_*HD_) + kvh*HD_ + c*8;
            CP_ASYNC16(sb + FK(p) + comp*16384 + sw256(r, c*16), src);
        }
        CP_COMMIT();
    };
    auto load_v = [&](int kt, int p) {
#pragma unroll
        for (int i = 0; i < 8; i++) {
            int idx = tid + (i << 8);
            int comp = idx >> 10, rem = idx & 1023;
            int r = rem >> 3, c = rem & 7;       // 128 d-rows x 8 chunks
            const bf16* src = (comp ? Vtl : Vth)
                + (size_t)((b*HK_ + kvh)*HD_ + r)*SEQ_ + kt*64 + c*8;
            CP_ASYNC16(sb + FV(p) + comp*16384 + sw128(r, c*16), src);
        }
        CP_COMMIT();
    };

    load_k(0, 0);
    load_v(0, 0);

    float o[16][4];
#pragma unroll
    for (int j = 0; j < 16; j++)
#pragma unroll
        for (int q = 0; q < 4; q++) o[j][q] = 0.f;
    float mr0 = -1e30f, mr1 = -1e30f, lr0s = 0.f, lr1s = 0.f;

    const int row0g = qbase + m0 + lr;

    for (int kt = 0; kt < niter; kt++) {
        const int p = kt & 1;
        cp_wait<1>();
        __syncthreads();
        if (kt + 1 < niter) { load_k(kt + 1, p ^ 1); load_v(kt + 1, p ^ 1); }

        const uint32_t kh_b = sb + FK(p);
        const uint32_t kl_b = kh_b + 16384;

        // ---- S = Q K^T (bf16x2, ldmatrix) ----
        float sa[8][4];
#pragma unroll
        for (int j = 0; j < 8; j++)
#pragma unroll
            for (int q = 0; q < 4; q++) sa[j][q] = 0.f;
#pragma unroll
        for (int s = 0; s < 8; s++) {
            const int b0 = s*32;
            uint32_t fqh[4], fql[4];
            uint32_t qaddr = sb + FQ_H + sw256(q_row, b0 + q_ofx);
            LDSM4(fqh[0], fqh[1], fqh[2], fqh[3], qaddr);
            LDSM4(fql[0], fql[1], fql[2], fql[3], qaddr + 32768);
#pragma unroll
            for (int jj = 0; jj < 4; jj++) {
                uint32_t fkh4[4], fkl4[4];
                uint32_t kaddr = sw256(kv_row + jj*16, b0 + kv_ofx);
                LDSM4(fkh4[0], fkh4[1], fkh4[2], fkh4[3], kh_b + kaddr);
                LDSM4(fkl4[0], fkl4[1], fkl4[2], fkl4[3], kl_b + kaddr);
#pragma unroll
                for (int half = 0; half < 2; half++) {
                    const int j = jj*2 + half;
                    uint32_t fkh[2] = { fkh4[half*2], fkh4[half*2+1] };
                    uint32_t fkl[2] = { fkl4[half*2], fkl4[half*2+1] };
                    mma16816(sa[j], fqh, fkh);
                    mma16816(sa[j], fql, fkh);
                    mma16816(sa[j], fqh, fkl);
                }
            }
        }

        // ---- online softmax ----
        const bool need_mask = (kt >= 2*qt);
        float mx0 = -1e30f, mx1 = -1e30f;
#pragma unroll
        for (int j = 0; j < 8; j++) {
            const int cb = kt*64 + j*8 + 2*lc;
#pragma unroll
            for (int q = 0; q < 4; q++) {
                float v = sa[j][q] * SCALE_;
                if (need_mask) {
                    int col = cb + (q & 1);
                    int row = (q < 2) ? row0g : (row0g + 8);
                    if (col > row) v = -1e30f;
                }
                sa[j][q] = v;
            }
            mx0 = fmaxf(mx0, fmaxf(sa[j][0], sa[j][1]));
            mx1 = fmaxf(mx1, fmaxf(sa[j][2], sa[j][3]));
        }
        mx0 = fmaxf(mx0, __shfl_xor_sync(0xffffffffu, mx0, 1));
        mx0 = fmaxf(mx0, __shfl_xor_sync(0xffffffffu, mx0, 2));
        mx1 = fmaxf(mx1, __shfl_xor_sync(0xffffffffu, mx1, 1));
        mx1 = fmaxf(mx1, __shfl_xor_sync(0xffffffffu, mx1, 2));
        const float mn0 = fmaxf(mr0, mx0);
        const float mn1 = fmaxf(mr1, mx1);
        const float c0 = __expf(mr0 - mn0);
        const float c1 = __expf(mr1 - mn1);
        float ps0 = 0.f, ps1 = 0.f;
#pragma unroll
        for (int j = 0; j < 8; j++) {
            sa[j][0] = __expf(sa[j][0] - mn0);
            sa[j][1] = __expf(sa[j][1] - mn0);
            sa[j][2] = __expf(sa[j][2] - mn1);
            sa[j][3] = __expf(sa[j][3] - mn1);
            ps0 += sa[j][0] + sa[j][1];
            ps1 += sa[j][2] + sa[j][3];
        }
        ps0 += __shfl_xor_sync(0xffffffffu, ps0, 1);
        ps0 += __shfl_xor_sync(0xffffffffu, ps0, 2);
        ps1 += __shfl_xor_sync(0xffffffffu, ps1, 1);
        ps1 += __shfl_xor_sync(0xffffffffu, ps1, 2);
        lr0s = lr0s * c0 + ps0;
        lr1s = lr1s * c1 + ps1;
        mr0 = mn0; mr1 = mn1;
#pragma unroll
        for (int j = 0; j < 16; j++) {
            o[j][0] *= c0; o[j][1] *= c0;
            o[j][2] *= c1; o[j][3] *= c1;
        }

        // ---- P frags directly from registers (S C-frag == PV A-frag) ----
        uint32_t aph[4][4], apl[4][4];
#pragma unroll
        for (int t = 0; t < 4; t++) {
            uint16_t h0,l0,h1,l1;
            bsplit(sa[2*t][0],h0,l0);   bsplit(sa[2*t][1],h1,l1);
            aph[t][0] = packb(h0,h1);   apl[t][0] = packb(l0,l1);
            bsplit(sa[2*t][2],h0,l0);   bsplit(sa[2*t][3],h1,l1);
            aph[t][1] = packb(h0,h1);   apl[t][1] = packb(l0,l1);
            bsplit(sa[2*t+1][0],h0,l0); bsplit(sa[2*t+1][1],h1,l1);
            aph[t][2] = packb(h0,h1);   apl[t][2] = packb(l0,l1);
            bsplit(sa[2*t+1][2],h0,l0); bsplit(sa[2*t+1][3],h1,l1);
            aph[t][3] = packb(h0,h1);   apl[t][3] = packb(l0,l1);
        }

        // ---- V ready ----
        if (kt + 1 < niter) cp_wait<2>(); else cp_wait<0>();
        __syncthreads();
        const uint32_t vh_b = sb + FV(p);
        const uint32_t vl_b = vh_b + 16384;

        // ---- O += P V (bf16x2, ldmatrix) ----
#pragma unroll
        for (int t = 0; t < 4; t++) {
            const int b0 = t*32;
#pragma unroll
            for (int jp = 0; jp < 8; jp++) {
                uint32_t fvh4[4], fvl4[4];
                uint32_t vaddr = sw128(kv_row + jp*16, b0 + kv_ofx);
                LDSM4(fvh4[0], fvh4[1], fvh4[2], fvh4[3], vh_b + vaddr);
                LDSM4(fvl4[0], fvl4[1], fvl4[2], fvl4[3], vl_b + vaddr);
#pragma unroll
                for (int half = 0; half < 2; half++) {
                    const int j = jp*2 + half;
                    uint32_t fvh[2] = { fvh4[half*2], fvh4[half*2+1] };
                    uint32_t fvl[2] = { fvl4[half*2], fvl4[half*2+1] };
                    mma16816(o[j], aph[t], fvh);
                    mma16816(o[j], apl[t], fvh);
                    mma16816(o[j], aph[t], fvl);
                }
            }
        }
    }

    // ---- normalize + split-store AO ----
    const float i0 = 1.f / lr0s;
    const float i1 = 1.f / lr1s;
    const size_t t0 = (size_t)(b*SEQ_ + row0g);
    const size_t t1 = t0 + 8;
#pragma unroll
    for (int j = 0; j < 16; j++) {
        const int col = h*HD_ + j*8 + 2*lc;
        uint16_t h0,l0,h1,l1;
        bsplit(o[j][0]*i0, h0, l0); bsplit(o[j][1]*i0, h1, l1);
        size_t off0 = t0*(HQ_*HD_) + col;
        *(uint32_t*)((char*)AOh + 2*off0) = packb(h0, h1);
        *(uint32_t*)((char*)AOl + 2*off0) = packb(l0, l1);
        bsplit(o[j][2]*i1, h0, l0); bsplit(o[j][3]*i1, h1, l1);
        size_t off1 = t1*(HQ_*HD_) + col;
        *(uint32_t*)((char*)AOh + 2*off1) = packb(h0, h1);
        *(uint32_t*)((char*)AOl + 2*off1) = packb(l0, l1);
    }
}

// ============================================================================
// Final per-token RMSNorm over DIM with attn_norm_w[expert]
// ============================================================================
__global__ __launch_bounds__(256) void final_rms(
    const float* __restrict__ in, const float* __restrict__ w,
    const int* __restrict__ mod, float* __restrict__ out)
{
    const int n = blockIdx.x;
    const int tid = threadIdx.x;
    const int e = mod[n];
    const float* row = in + (size_t)n*DIM_;
    float vals[8];
    float ss = 0.f;
#pragma unroll
    for (int u = 0; u < 8; u++) {
        float v = row[tid + u*256];
        vals[u] = v;
        ss += v*v;
    }
#pragma unroll
    for (int o = 16; o > 0; o >>= 1) ss += __shfl_xor_sync(0xffffffffu, ss, o);
    __shared__ float wsum[8];
    if ((tid & 31) == 0) wsum[tid >> 5] = ss;
    __syncthreads();
    float tot = 0.f;
#pragma unroll
    for (int i = 0; i < 8; i++) tot += wsum[i];
    float r = rsqrtf(tot * (1.0f/DIM_) + EPS_);
#pragma unroll
    for (int u = 0; u < 8; u++)
        out[(size_t)n*DIM_ + tid + u*256] = vals[u] * r * w[e*DIM_ + tid + u*256];
}

// ============================================================================
// launch
// ============================================================================
extern "C" void kernel_launch(void* const* d_in, const int* in_sizes, int n_in,
                              void* d_out, int out_size)
{
    const float* x    = (const float*)d_in[0];
    const float* fcos = (const float*)d_in[1];
    const float* fsin = (const float*)d_in[2];
    const float* wq   = (const float*)d_in[3];
    const float* wk   = (const float*)d_in[4];
    const float* wv   = (const float*)d_in[5];
    const float* wo   = (const float*)d_in[6];
    const float* qnw  = (const float*)d_in[7];
    const float* knw  = (const float*)d_in[8];
    const float* anw  = (const float*)d_in[9];
    const int*   mod  = (const int*)d_in[10];
    float* out = (float*)d_out;

    float *pv, *po;
    bf16 *pxh, *pxl, *pwqh, *pwql, *pwkh, *pwkl, *pwvh, *pwvl, *pwoh, *pwol;
    bf16 *pqh, *pql, *pkh, *pkl, *pvth, *pvtl, *paoh, *paol;
    cudaGetSymbolAddress((void**)&pv,  g_v);
    cudaGetSymbolAddress((void**)&po,  g_o);
    cudaGetSymbolAddress((void**)&pxh, g_xh);  cudaGetSymbolAddress((void**)&pxl, g_xl);
    cudaGetSymbolAddress((void**)&pwqh, g_wqh); cudaGetSymbolAddress((void**)&pwql, g_wql);
    cudaGetSymbolAddress((void**)&pwkh, g_wkh); cudaGetSymbolAddress((void**)&pwkl, g_wkl);
    cudaGetSymbolAddress((void**)&pwvh, g_wvh); cudaGetSymbolAddress((void**)&pwvl, g_wvl);
    cudaGetSymbolAddress((void**)&pwoh, g_woh); cudaGetSymbolAddress((void**)&pwol, g_wol);
    cudaGetSymbolAddress((void**)&pqh, g_qh);   cudaGetSymbolAddress((void**)&pql, g_ql);
    cudaGetSymbolAddress((void**)&pkh, g_kh);   cudaGetSymbolAddress((void**)&pkl, g_kl);
    cudaGetSymbolAddress((void**)&pvth, g_vth); cudaGetSymbolAddress((void**)&pvtl, g_vtl);
    cudaGetSymbolAddress((void**)&paoh, g_aoh); cudaGetSymbolAddress((void**)&paol, g_aol);

    cudaFuncSetAttribute(flash_attn, cudaFuncAttributeMaxDynamicSharedMemorySize, FA_BYTES);
    cudaFuncSetAttribute(mm_bf16<0>, cudaFuncAttributeMaxDynamicSharedMemorySize, MM_DSMEM);
    cudaFuncSetAttribute(mm_bf16<1>, cudaFuncAttributeMaxDynamicSharedMemorySize, MM_DSMEM);

    // preprocessing
    sort_tokens<<<1, 1024>>>(mod);
    split_f32<<<(NTOK*DIM_/4 + 255)/256, 256>>>(x, pxh, pxl, NTOK*DIM_/4);
    wtrans_split<<<dim3(64, 64, 2), 256>>>(wq, pwqh, pwql, DIM_, HQ_*HD_);
    wtrans_split<<<dim3(64, 32, 2), 256>>>(wk, pwkh, pwkl, DIM_, HK_*HD_);
    wtrans_split<<<dim3(64, 32, 2), 256>>>(wv, pwvh, pwvl, DIM_, HK_*HD_);
    wtrans_split<<<dim3(64, 64, 2), 256>>>(wo, pwoh, pwol, HQ_*HD_, DIM_);

    // Q/K projections with fused rmsnorm+rope -> bf16 split outputs
    mm_bf16<1><<<dim3(16, 33), 128, MM_DSMEM>>>(pxh, pxl, pwqh, pwql,
        nullptr, pqh, pql, qnw, fcos, fsin, DIM_, HQ_*HD_);
    mm_bf16<1><<<dim3( 8, 33), 128, MM_DSMEM>>>(pxh, pxl, pwkh, pwkl,
        nullptr, pkh, pkl, knw, fcos, fsin, DIM_, HK_*HD_);
    // V projection (fp32) + transpose-split
    mm_bf16<0><<<dim3( 8, 33), 128, MM_DSMEM>>>(pxh, pxl, pwvh, pwvl,
        pv, nullptr, nullptr, nullptr, nullptr, nullptr, DIM_, HK_*HD_);
    vtrans_split<<<dim3(64, 4, 16), 256>>>(pv, pvth, pvtl);

    // attention (P register-resident, ldmatrix)
    flash_attn<<<dim3(16, HQ_, BS_), 256, FA_BYTES>>>(pqh, pql, pkh, pkl, pvth, pvtl, paoh, paol);

    // output projection + final rmsnorm
    mm_bf16<0><<<dim3(16, 33), 128, MM_DSMEM>>>(paoh, paol, pwoh, pwol,
        po, nullptr, nullptr, nullptr, nullptr, nullptr, HQ_*HD_, DIM_);
    final_rms<<<NTOK, 256>>>(po, anw, mod, out);
}